// round 6
// baseline (speedup 1.0000x reference)
#include <cuda_runtime.h>
#include <math_constants.h>
#include <cstdint>

#define BATCH 4
#define SEQ   2048
#define EMB   1024
#define KD    1024

#define BM 128
#define BN 256
#define BKK 32                        // k per stage; 32 floats = 128B row

#define A_STG 16384                   // 128 rows x 128B
#define B_STG 32768                   // 256 rows x 128B
#define SM_B  (3 * A_STG)             // 3-stage A, then 3-stage B
#define SMEM_TOTAL (3 * (A_STG + B_STG))   // 147456; transpose buf 135168 fits

// ---------------- static device scratch ----------------
__device__ float g_x [BATCH * SEQ * EMB];
__device__ float g_Wq[KD * EMB];
__device__ float g_Wk[KD * EMB];
__device__ float g_Wv[EMB * EMB];
__device__ float g_Q [BATCH * SEQ * KD];
__device__ float g_K [BATCH * SEQ * KD];
__device__ float g_Vt[BATCH * EMB * SEQ];            // V transposed [b][e][s]
__device__ float g_P [(long long)BATCH * SEQ * SEQ];

// ---------------- helpers ----------------
__device__ __forceinline__ float tf32r(float x) {
    unsigned r; asm("cvt.rna.tf32.f32 %0, %1;" : "=r"(r) : "f"(x));
    return __uint_as_float(r);
}
__device__ __forceinline__ void cp_async16(uint32_t d, const void* g) {
    asm volatile("cp.async.cg.shared.global [%0], [%1], 16;\n" :: "r"(d), "l"(g));
}
#define CP_COMMIT() asm volatile("cp.async.commit_group;\n" ::: "memory")
#define CP_WAIT(n)  asm volatile("cp.async.wait_group %0;\n" :: "n"(n) : "memory")

__device__ __forceinline__ void ldsm_x4(uint32_t r[4], uint32_t addr) {
    asm volatile("ldmatrix.sync.aligned.m8n8.x4.shared.b16 {%0,%1,%2,%3}, [%4];"
        : "=r"(r[0]), "=r"(r[1]), "=r"(r[2]), "=r"(r[3]) : "r"(addr));
}
__device__ __forceinline__ void mma_tf32(float d[4], const uint32_t a[4], const uint32_t b[2]) {
    asm volatile(
        "mma.sync.aligned.m16n8k8.row.col.f32.tf32.tf32.f32 "
        "{%0,%1,%2,%3}, {%4,%5,%6,%7}, {%8,%9}, {%0,%1,%2,%3};\n"
        : "+f"(d[0]), "+f"(d[1]), "+f"(d[2]), "+f"(d[3])
        : "r"(a[0]), "r"(a[1]), "r"(a[2]), "r"(a[3]), "r"(b[0]), "r"(b[1]));
}

// ---------------- GEMM core: C[m,n] = alpha * A[m,:]·B[n,:], both K-major ----------------
// Inputs must be pre-rounded to tf32 bit patterns (no CVT in mainloop).
// 8 warps: 2 (M) x 4 (N), warp tile 64x64.
// EPI: 0 = store acc*alpha; 1 = store tf32r(acc); 2 = transposed tf32r store into Vt
template<int EPI>
__device__ __forceinline__ void gemm_core(
    const float* __restrict__ A, const float* __restrict__ B, float* __restrict__ C,
    int lda, int ldb, long long ldc, int m0, int n0, int kEnd, float alpha)
{
    extern __shared__ char smraw[];
    const uint32_t sb = (uint32_t)__cvta_generic_to_shared(smraw);
    const int tid  = threadIdx.x;
    const int lane = tid & 31;
    const int warp = tid >> 5;
    const int wm   = warp & 1;          // 64-row slab
    const int wn   = warp >> 1;         // 0..3 -> 64-col slab
    const int g    = lane >> 2;         // 0..7
    const int tg   = lane & 3;          // 0..3

    // ldmatrix lane constants
    const int u   = lane & 7;
    const int j   = lane >> 3;
    const int c0A = j >> 1;             // k-chunk select for A matrices
    const int rA  = (j & 1) * 8 + u;    // row within 16-row tile
    const int c0B = j & 1;              // k-chunk select for B matrices
    const int nB  = (j >> 1) * 8 + u;   // n within 16-col group

    float acc[4][8][4];
    #pragma unroll
    for (int mt = 0; mt < 4; mt++)
        #pragma unroll
        for (int nt = 0; nt < 8; nt++)
            #pragma unroll
            for (int i = 0; i < 4; i++) acc[mt][nt][i] = 0.0f;

    const int nk = kEnd / BKK;          // >= 4 for all call sites

    auto load_stage = [&](int s, int k0) {
        #pragma unroll
        for (int i = 0; i < 4; i++) {            // A: 128 rows x 128B, sw128
            int c = tid + i * 256;
            int row = c >> 3, ch = c & 7;
            uint32_t sa = sb + (uint32_t)(s * A_STG + row * 128 + ((ch ^ (row & 7)) * 16));
            cp_async16(sa, &A[(long long)(m0 + row) * lda + k0 + ch * 4]);
        }
        #pragma unroll
        for (int i = 0; i < 8; i++) {            // B: 256 rows x 128B, sw128
            int c = tid + i * 256;
            int row = c >> 3, ch = c & 7;
            uint32_t sa = sb + (uint32_t)(SM_B + s * B_STG + row * 128 + ((ch ^ (row & 7)) * 16));
            cp_async16(sa, &B[(long long)(n0 + row) * ldb + k0 + ch * 4]);
        }
    };

    load_stage(0, 0); CP_COMMIT();
    load_stage(1, BKK); CP_COMMIT();

    for (int it = 0; it < nk; ++it) {
        if (it + 2 < nk) load_stage((it + 2) % 3, (it + 2) * BKK);
        CP_COMMIT();
        CP_WAIT(2);
        __syncthreads();

        const uint32_t aBase = sb + (uint32_t)((it % 3) * A_STG);
        const uint32_t bBase = sb + (uint32_t)(SM_B + (it % 3) * B_STG);

        #pragma unroll
        for (int ks = 0; ks < 4; ks++) {
            uint32_t af[4][4], bf[4][4];
            #pragma unroll
            for (int mt = 0; mt < 4; mt++) {
                int row = wm * 64 + mt * 16 + rA;
                ldsm_x4(af[mt], aBase + (uint32_t)(row * 128 + (((c0A + 2 * ks) ^ u) * 16)));
            }
            #pragma unroll
            for (int h = 0; h < 4; h++) {
                int n = wn * 64 + h * 16 + nB;
                ldsm_x4(bf[h], bBase + (uint32_t)(n * 128 + (((c0B + 2 * ks) ^ u) * 16)));
            }
            #pragma unroll
            for (int mt = 0; mt < 4; mt++)
                #pragma unroll
                for (int nt = 0; nt < 8; nt++)
                    mma_tf32(acc[mt][nt], af[mt], &bf[nt >> 1][(nt & 1) * 2]);
        }
        __syncthreads();
    }

    // ---- epilogue ----
    if (EPI == 2) {
        // transpose 128(s) x 256(e) tile through smem -> Vt[e][s], coalesced
        float* sT = (float*)smraw;               // [256 e][stride 132]
        #pragma unroll
        for (int mt = 0; mt < 4; mt++)
            #pragma unroll
            for (int nt = 0; nt < 8; nt++)
                #pragma unroll
                for (int i = 0; i < 4; i++) {
                    int rl = wm * 64 + mt * 16 + g + (i >> 1) * 8;
                    int cl = wn * 64 + nt * 8 + 2 * tg + (i & 1);
                    sT[cl * 132 + rl] = tf32r(acc[mt][nt][i]);
                }
        __syncthreads();
        int b  = m0 >> 11;
        int s0 = m0 & 2047;
        float* dst = C + ((long long)b * EMB + n0) * (long long)SEQ + s0;
        #pragma unroll
        for (int i = 0; i < 32; i++) {
            int idx = tid + i * 256;
            int er = idx >> 5, sc = (idx & 31) * 4;
            float4 v = *(const float4*)&sT[er * 132 + sc];
            *(float4*)&dst[(long long)er * SEQ + sc] = v;
        }
        __syncthreads();
    } else {
        #pragma unroll
        for (int mt = 0; mt < 4; mt++) {
            const long long r0 = m0 + wm * 64 + mt * 16 + g;
            const long long r1 = r0 + 8;
            #pragma unroll
            for (int nt = 0; nt < 8; nt++) {
                const int cc = n0 + wn * 64 + nt * 8 + 2 * tg;
                float2 v0, v1;
                if (EPI == 1) {
                    v0 = make_float2(tf32r(acc[mt][nt][0]), tf32r(acc[mt][nt][1]));
                    v1 = make_float2(tf32r(acc[mt][nt][2]), tf32r(acc[mt][nt][3]));
                } else {
                    v0 = make_float2(acc[mt][nt][0] * alpha, acc[mt][nt][1] * alpha);
                    v1 = make_float2(acc[mt][nt][2] * alpha, acc[mt][nt][3] * alpha);
                }
                *(float2*)&C[r0 * ldc + cc] = v0;
                *(float2*)&C[r1 * ldc + cc] = v1;
            }
        }
    }
}

// ---------------- kernels ----------------

__global__ void round_kernel(const float* __restrict__ src, int which, int n4) {
    int i = blockIdx.x * blockDim.x + threadIdx.x;
    if (i >= n4) return;
    float* dst = (which == 0) ? g_x : (which == 1) ? g_Wq : (which == 2) ? g_Wk : g_Wv;
    float4 v = ((const float4*)src)[i];
    v.x = tf32r(v.x); v.y = tf32r(v.y); v.z = tf32r(v.z); v.w = tf32r(v.w);
    ((float4*)dst)[i] = v;
}

// grid (EMB/BN=4, 8192/BM=64, 3)
__global__ __launch_bounds__(256, 1)
void proj_kernel()
{
    int z = blockIdx.z;
    const float* W = (z == 0) ? g_Wq : (z == 1) ? g_Wk : g_Wv;
    if (z == 2)
        gemm_core<2>(g_x, W, g_Vt, EMB, EMB, 0,
                     blockIdx.y * BM, blockIdx.x * BN, EMB, 1.0f);
    else
        gemm_core<1>(g_x, W, (z == 0) ? g_Q : g_K, EMB, EMB, KD,
                     blockIdx.y * BM, blockIdx.x * BN, EMB, 1.0f);
}

// grid (SEQ/BN=8, SEQ/BM=16, 4): keep tile iff bx*256 <= by*128+127 -> 2bx <= by
__global__ __launch_bounds__(256, 1)
void scores_kernel()
{
    int b = blockIdx.z, by = blockIdx.y, bx = blockIdx.x;
    if (2 * bx > by) return;
    gemm_core<0>(g_Q + (long long)b * SEQ * KD, g_K + (long long)b * SEQ * KD,
                 g_P + (long long)b * SEQ * SEQ, KD, KD, SEQ,
                 by * BM, bx * BN, KD, 0.03125f);
}

__global__ __launch_bounds__(256)
void softmax_kernel()
{
    __shared__ float sr[SEQ];
    __shared__ float red[256];
    int b = blockIdx.y, q = blockIdx.x, tid = threadIdx.x;
    float* row = g_P + ((long long)b * SEQ + q) * SEQ;
    int n = q + 1;

    float m = -CUDART_INF_F;
    for (int jx = tid; jx < n; jx += 256) { float v = row[jx]; sr[jx] = v; m = fmaxf(m, v); }
    red[tid] = m; __syncthreads();
    #pragma unroll
    for (int s = 128; s > 0; s >>= 1) {
        if (tid < s) red[tid] = fmaxf(red[tid], red[tid + s]);
        __syncthreads();
    }
    m = red[0];
    __syncthreads();

    float sum = 0.0f;
    for (int jx = tid; jx < n; jx += 256) { float e = __expf(sr[jx] - m); sr[jx] = e; sum += e; }
    red[tid] = sum; __syncthreads();
    #pragma unroll
    for (int s = 128; s > 0; s >>= 1) {
        if (tid < s) red[tid] += red[tid + s];
        __syncthreads();
    }
    float inv = 1.0f / red[0];

    for (int jx = tid; jx < n; jx += 256) row[jx] = tf32r(sr[jx] * inv);
    // zero only up to the 128-boundary actually read by out_kernel's k-trim
    int zend = ((q >> 7) + 1) << 7;
    for (int jx = n + tid; jx < zend; jx += 256) row[jx] = 0.0f;
}

// grid (EMB/BN=4, SEQ/BM=16, 4); causal k-trim
__global__ __launch_bounds__(256, 1)
void out_kernel(float* __restrict__ out)
{
    int b = blockIdx.z, by = blockIdx.y;
    gemm_core<0>(g_P + (long long)b * SEQ * SEQ, g_Vt + (long long)b * EMB * SEQ,
                 out + (long long)b * SEQ * EMB, SEQ, SEQ, EMB,
                 by * BM, blockIdx.x * BN, (by + 1) * BM, 1.0f);
}

// ---------------- launch ----------------
extern "C" void kernel_launch(void* const* d_in, const int* in_sizes, int n_in,
                              void* d_out, int out_size)
{
    const float* x  = (const float*)d_in[0];
    const float* Wq = (const float*)d_in[1];
    const float* Wk = (const float*)d_in[2];
    const float* Wv = (const float*)d_in[3];
    float* out = (float*)d_out;

    cudaFuncSetAttribute(proj_kernel,   cudaFuncAttributeMaxDynamicSharedMemorySize, SMEM_TOTAL);
    cudaFuncSetAttribute(scores_kernel, cudaFuncAttributeMaxDynamicSharedMemorySize, SMEM_TOTAL);
    cudaFuncSetAttribute(out_kernel,    cudaFuncAttributeMaxDynamicSharedMemorySize, SMEM_TOTAL);

    round_kernel<<<(BATCH * SEQ * EMB / 4 + 255) / 256, 256>>>(x, 0, BATCH * SEQ * EMB / 4);
    round_kernel<<<(KD * EMB / 4 + 255) / 256, 256>>>(Wq, 1, KD * EMB / 4);
    round_kernel<<<(KD * EMB / 4 + 255) / 256, 256>>>(Wk, 2, KD * EMB / 4);
    round_kernel<<<(EMB * EMB / 4 + 255) / 256, 256>>>(Wv, 3, EMB * EMB / 4);

    proj_kernel<<<dim3(EMB / BN, (BATCH * SEQ) / BM, 3), 256, SMEM_TOTAL>>>();
    scores_kernel<<<dim3(SEQ / BN, SEQ / BM, BATCH), 256, SMEM_TOTAL>>>();
    softmax_kernel<<<dim3(SEQ, BATCH), 256>>>();
    out_kernel<<<dim3(EMB / BN, SEQ / BM, BATCH), 256, SMEM_TOTAL>>>(out);
}

// round 7
// speedup vs baseline: 1.1675x; 1.1675x over previous
#include <cuda_runtime.h>
#include <math_constants.h>
#include <cstdint>

#define BATCH 4
#define SEQ   2048
#define EMB   1024
#define KD    1024

#define BM 128
#define BN 128
#define BKK 32                        // k per stage; 32 floats = 128B row

#define A_STG 16384                   // 128 rows x 128B
#define B_STG 16384
#define SM_B  (2 * A_STG)             // double-buffered A then B
#define SMEM_TOTAL 67584              // max(64KB pipeline, 128*132*4 transpose buf)

#define NTHREADS 128                  // 4 warps, 2(M) x 2(N), warp tile 64x64

// ---------------- static device scratch ----------------
__device__ float g_x [BATCH * SEQ * EMB];
__device__ float g_Wq[KD * EMB];
__device__ float g_Wk[KD * EMB];
__device__ float g_Wv[EMB * EMB];
__device__ float g_Q [BATCH * SEQ * KD];
__device__ float g_K [BATCH * SEQ * KD];
__device__ float g_Vt[BATCH * EMB * SEQ];            // V transposed [b][e][s]
__device__ float g_P [(long long)BATCH * SEQ * SEQ];

// ---------------- helpers ----------------
__device__ __forceinline__ float tf32r(float x) {
    unsigned r; asm("cvt.rna.tf32.f32 %0, %1;" : "=r"(r) : "f"(x));
    return __uint_as_float(r);
}
__device__ __forceinline__ void cp_async16(uint32_t d, const void* g) {
    asm volatile("cp.async.cg.shared.global [%0], [%1], 16;\n" :: "r"(d), "l"(g));
}
#define CP_COMMIT() asm volatile("cp.async.commit_group;\n" ::: "memory")
#define CP_WAIT(n)  asm volatile("cp.async.wait_group %0;\n" :: "n"(n) : "memory")

__device__ __forceinline__ void ldsm_x4(uint32_t r[4], uint32_t addr) {
    asm volatile("ldmatrix.sync.aligned.m8n8.x4.shared.b16 {%0,%1,%2,%3}, [%4];"
        : "=r"(r[0]), "=r"(r[1]), "=r"(r[2]), "=r"(r[3]) : "r"(addr));
}
__device__ __forceinline__ void mma_tf32(float d[4], const uint32_t a[4], const uint32_t b[2]) {
    asm volatile(
        "mma.sync.aligned.m16n8k8.row.col.f32.tf32.tf32.f32 "
        "{%0,%1,%2,%3}, {%4,%5,%6,%7}, {%8,%9}, {%0,%1,%2,%3};\n"
        : "+f"(d[0]), "+f"(d[1]), "+f"(d[2]), "+f"(d[3])
        : "r"(a[0]), "r"(a[1]), "r"(a[2]), "r"(a[3]), "r"(b[0]), "r"(b[1]));
}

// ---------------- GEMM core: C[m,n] = alpha * A[m,:]·B[n,:], both K-major ----------------
// Inputs pre-rounded to tf32 bit patterns (no CVT in mainloop).
// 4 warps (2x2), warp tile 64x64, 128x128 block tile, double-buffered.
// EPI: 0 = store acc*alpha; 1 = store tf32r(acc); 2 = transposed tf32r store into Vt
template<int EPI>
__device__ __forceinline__ void gemm_core(
    const float* __restrict__ A, const float* __restrict__ B, float* __restrict__ C,
    int lda, int ldb, long long ldc, int m0, int n0, int kEnd, float alpha)
{
    extern __shared__ char smraw[];
    const uint32_t sb = (uint32_t)__cvta_generic_to_shared(smraw);
    const int tid  = threadIdx.x;
    const int lane = tid & 31;
    const int warp = tid >> 5;
    const int wm   = warp & 1;          // 64-row slab
    const int wn   = warp >> 1;         // 64-col slab
    const int g    = lane >> 2;         // 0..7
    const int tg   = lane & 3;          // 0..3

    // ldmatrix lane constants
    const int u   = lane & 7;
    const int j   = lane >> 3;
    const int c0A = j >> 1;             // k-chunk select for A matrices
    const int rA  = (j & 1) * 8 + u;    // row within 16-row tile
    const int c0B = j & 1;              // k-chunk select for B matrices
    const int nB  = (j >> 1) * 8 + u;   // n within 16-col group

    float acc[4][8][4];
    #pragma unroll
    for (int mt = 0; mt < 4; mt++)
        #pragma unroll
        for (int nt = 0; nt < 8; nt++)
            #pragma unroll
            for (int i = 0; i < 4; i++) acc[mt][nt][i] = 0.0f;

    const int nk = kEnd / BKK;

    auto load_stage = [&](int s, int k0) {
        #pragma unroll
        for (int i = 0; i < 8; i++) {            // A: 128 rows x 128B, sw128
            int c = tid + i * NTHREADS;
            int row = c >> 3, ch = c & 7;
            uint32_t sa = sb + (uint32_t)(s * A_STG + row * 128 + ((ch ^ (row & 7)) * 16));
            cp_async16(sa, &A[(long long)(m0 + row) * lda + k0 + ch * 4]);
        }
        #pragma unroll
        for (int i = 0; i < 8; i++) {            // B: 128 rows x 128B, sw128
            int c = tid + i * NTHREADS;
            int row = c >> 3, ch = c & 7;
            uint32_t sa = sb + (uint32_t)(SM_B + s * B_STG + row * 128 + ((ch ^ (row & 7)) * 16));
            cp_async16(sa, &B[(long long)(n0 + row) * ldb + k0 + ch * 4]);
        }
    };

    load_stage(0, 0);
    CP_COMMIT();

    for (int it = 0; it < nk; ++it) {
        if (it + 1 < nk) {
            load_stage((it + 1) & 1, (it + 1) * BKK);
            CP_COMMIT();
            CP_WAIT(1);
        } else {
            CP_WAIT(0);
        }
        __syncthreads();

        const uint32_t aBase = sb + (uint32_t)((it & 1) * A_STG);
        const uint32_t bBase = sb + (uint32_t)(SM_B + (it & 1) * B_STG);

        #pragma unroll
        for (int ks = 0; ks < 4; ks++) {
            uint32_t af[4][4], bf[4][4];
            #pragma unroll
            for (int mt = 0; mt < 4; mt++) {
                int row = wm * 64 + mt * 16 + rA;
                ldsm_x4(af[mt], aBase + (uint32_t)(row * 128 + (((c0A + 2 * ks) ^ u) * 16)));
            }
            #pragma unroll
            for (int h = 0; h < 4; h++) {
                int n = wn * 64 + h * 16 + nB;
                ldsm_x4(bf[h], bBase + (uint32_t)(n * 128 + (((c0B + 2 * ks) ^ u) * 16)));
            }
            #pragma unroll
            for (int mt = 0; mt < 4; mt++)
                #pragma unroll
                for (int nt = 0; nt < 8; nt++)
                    mma_tf32(acc[mt][nt], af[mt], &bf[nt >> 1][(nt & 1) * 2]);
        }
        __syncthreads();
    }

    // ---- epilogue ----
    if (EPI == 2) {
        // transpose 128(s) x 128(e) tile through smem -> Vt[e][s], coalesced
        float* sT = (float*)smraw;               // [128 e][stride 132]
        #pragma unroll
        for (int mt = 0; mt < 4; mt++)
            #pragma unroll
            for (int nt = 0; nt < 8; nt++)
                #pragma unroll
                for (int i = 0; i < 4; i++) {
                    int rl = wm * 64 + mt * 16 + g + (i >> 1) * 8;
                    int cl = wn * 64 + nt * 8 + 2 * tg + (i & 1);
                    sT[cl * 132 + rl] = tf32r(acc[mt][nt][i]);
                }
        __syncthreads();
        int b  = m0 >> 11;
        int s0 = m0 & 2047;
        float* dst = C + ((long long)b * EMB + n0) * (long long)SEQ + s0;
        #pragma unroll
        for (int i = 0; i < 32; i++) {
            int idx = tid + i * NTHREADS;
            int er = idx >> 5, sc = (idx & 31) * 4;
            float4 v = *(const float4*)&sT[er * 132 + sc];
            *(float4*)&dst[(long long)er * SEQ + sc] = v;
        }
        __syncthreads();
    } else {
        #pragma unroll
        for (int mt = 0; mt < 4; mt++) {
            const long long r0 = m0 + wm * 64 + mt * 16 + g;
            const long long r1 = r0 + 8;
            #pragma unroll
            for (int nt = 0; nt < 8; nt++) {
                const int cc = n0 + wn * 64 + nt * 8 + 2 * tg;
                float2 v0, v1;
                if (EPI == 1) {
                    v0 = make_float2(tf32r(acc[mt][nt][0]), tf32r(acc[mt][nt][1]));
                    v1 = make_float2(tf32r(acc[mt][nt][2]), tf32r(acc[mt][nt][3]));
                } else {
                    v0 = make_float2(acc[mt][nt][0] * alpha, acc[mt][nt][1] * alpha);
                    v1 = make_float2(acc[mt][nt][2] * alpha, acc[mt][nt][3] * alpha);
                }
                *(float2*)&C[r0 * ldc + cc] = v0;
                *(float2*)&C[r1 * ldc + cc] = v1;
            }
        }
    }
}

// ---------------- kernels ----------------

__global__ void round_kernel(const float* __restrict__ src, int which, int n4) {
    int i = blockIdx.x * blockDim.x + threadIdx.x;
    if (i >= n4) return;
    float* dst = (which == 0) ? g_x : (which == 1) ? g_Wq : (which == 2) ? g_Wk : g_Wv;
    float4 v = ((const float4*)src)[i];
    v.x = tf32r(v.x); v.y = tf32r(v.y); v.z = tf32r(v.z); v.w = tf32r(v.w);
    ((float4*)dst)[i] = v;
}

// grid (KD/BN=8, 8192/BM=64, 3)
__global__ __launch_bounds__(NTHREADS, 2)
void proj_kernel()
{
    int z = blockIdx.z;
    const float* W = (z == 0) ? g_Wq : (z == 1) ? g_Wk : g_Wv;
    if (z == 2)
        gemm_core<2>(g_x, W, g_Vt, EMB, EMB, 0,
                     blockIdx.y * BM, blockIdx.x * BN, EMB, 1.0f);
    else
        gemm_core<1>(g_x, W, (z == 0) ? g_Q : g_K, EMB, EMB, KD,
                     blockIdx.y * BM, blockIdx.x * BN, EMB, 1.0f);
}

// grid (16, 16, 4); skip fully-masked tiles
__global__ __launch_bounds__(NTHREADS, 2)
void scores_kernel()
{
    int b = blockIdx.z, bq = blockIdx.y, bs = blockIdx.x;
    if (bs > bq) return;
    gemm_core<0>(g_Q + (long long)b * SEQ * KD, g_K + (long long)b * SEQ * KD,
                 g_P + (long long)b * SEQ * SEQ, KD, KD, SEQ,
                 bq * BM, bs * BN, KD, 0.03125f);
}

__global__ __launch_bounds__(256)
void softmax_kernel()
{
    __shared__ float sr[SEQ];
    __shared__ float red[256];
    int b = blockIdx.y, q = blockIdx.x, tid = threadIdx.x;
    float* row = g_P + ((long long)b * SEQ + q) * SEQ;
    int n = q + 1;

    float m = -CUDART_INF_F;
    for (int jx = tid; jx < n; jx += 256) { float v = row[jx]; sr[jx] = v; m = fmaxf(m, v); }
    red[tid] = m; __syncthreads();
    #pragma unroll
    for (int s = 128; s > 0; s >>= 1) {
        if (tid < s) red[tid] = fmaxf(red[tid], red[tid + s]);
        __syncthreads();
    }
    m = red[0];
    __syncthreads();

    float sum = 0.0f;
    for (int jx = tid; jx < n; jx += 256) { float e = __expf(sr[jx] - m); sr[jx] = e; sum += e; }
    red[tid] = sum; __syncthreads();
    #pragma unroll
    for (int s = 128; s > 0; s >>= 1) {
        if (tid < s) red[tid] += red[tid + s];
        __syncthreads();
    }
    float inv = 1.0f / red[0];

    for (int jx = tid; jx < n; jx += 256) row[jx] = tf32r(sr[jx] * inv);
    // zero only up to the 128-boundary actually read by out_kernel's k-trim
    int zend = ((q >> 7) + 1) << 7;
    for (int jx = n + tid; jx < zend; jx += 256) row[jx] = 0.0f;
}

// grid (8, 16, 4); causal k-trim
__global__ __launch_bounds__(NTHREADS, 2)
void out_kernel(float* __restrict__ out)
{
    int b = blockIdx.z, bq = blockIdx.y;
    gemm_core<0>(g_P + (long long)b * SEQ * SEQ, g_Vt + (long long)b * EMB * SEQ,
                 out + (long long)b * SEQ * EMB, SEQ, SEQ, EMB,
                 bq * BM, blockIdx.x * BN, (bq + 1) * BM, 1.0f);
}

// ---------------- launch ----------------
extern "C" void kernel_launch(void* const* d_in, const int* in_sizes, int n_in,
                              void* d_out, int out_size)
{
    const float* x  = (const float*)d_in[0];
    const float* Wq = (const float*)d_in[1];
    const float* Wk = (const float*)d_in[2];
    const float* Wv = (const float*)d_in[3];
    float* out = (float*)d_out;

    cudaFuncSetAttribute(proj_kernel,   cudaFuncAttributeMaxDynamicSharedMemorySize, SMEM_TOTAL);
    cudaFuncSetAttribute(scores_kernel, cudaFuncAttributeMaxDynamicSharedMemorySize, SMEM_TOTAL);
    cudaFuncSetAttribute(out_kernel,    cudaFuncAttributeMaxDynamicSharedMemorySize, SMEM_TOTAL);

    round_kernel<<<(BATCH * SEQ * EMB / 4 + 255) / 256, 256>>>(x, 0, BATCH * SEQ * EMB / 4);
    round_kernel<<<(KD * EMB / 4 + 255) / 256, 256>>>(Wq, 1, KD * EMB / 4);
    round_kernel<<<(KD * EMB / 4 + 255) / 256, 256>>>(Wk, 2, KD * EMB / 4);
    round_kernel<<<(EMB * EMB / 4 + 255) / 256, 256>>>(Wv, 3, EMB * EMB / 4);

    proj_kernel<<<dim3(KD / BN, (BATCH * SEQ) / BM, 3), NTHREADS, SMEM_TOTAL>>>();
    scores_kernel<<<dim3(SEQ / BN, SEQ / BM, BATCH), NTHREADS, SMEM_TOTAL>>>();
    softmax_kernel<<<dim3(SEQ, BATCH), 256>>>();
    out_kernel<<<dim3(EMB / BN, SEQ / BM, BATCH), NTHREADS, SMEM_TOTAL>>>(out);
}

// round 8
// speedup vs baseline: 1.2268x; 1.0508x over previous
#include <cuda_runtime.h>
#include <math_constants.h>
#include <cstdint>

#define BATCH 4
#define SEQ   2048
#define EMB   1024
#define KD    1024

#define BM 128
#define BN 128
#define BKK 32                        // k per stage; 32 floats = 128B row

#define A_STG 16384                   // 128 rows x 128B
#define B_STG 16384
#define SM_B  (2 * A_STG)             // double-buffered A then B
#define SMEM_TOTAL 67584              // max(64KB pipeline, 128*132*4 transpose buf)

#define NTHREADS 128                  // 4 warps, 2(M) x 2(N), warp tile 64x64

// ---------------- static device scratch ----------------
__device__ float g_x [BATCH * SEQ * EMB];
__device__ float g_Wq[KD * EMB];
__device__ float g_Wk[KD * EMB];
__device__ float g_Wv[EMB * EMB];
__device__ float g_Q [BATCH * SEQ * KD];
__device__ float g_K [BATCH * SEQ * KD];
__device__ float g_Vt[BATCH * EMB * SEQ];            // V transposed [b][e][s]
__device__ float g_P [(long long)BATCH * SEQ * SEQ]; // exp(scores), unnormalized
__device__ float g_rowsum[BATCH * SEQ];              // per-row sum of exp

// ---------------- helpers ----------------
__device__ __forceinline__ float tf32r(float x) {
    unsigned r; asm("cvt.rna.tf32.f32 %0, %1;" : "=r"(r) : "f"(x));
    return __uint_as_float(r);
}
__device__ __forceinline__ void cp_async16(uint32_t d, const void* g) {
    asm volatile("cp.async.cg.shared.global [%0], [%1], 16;\n" :: "r"(d), "l"(g));
}
#define CP_COMMIT() asm volatile("cp.async.commit_group;\n" ::: "memory")
#define CP_WAIT(n)  asm volatile("cp.async.wait_group %0;\n" :: "n"(n) : "memory")

__device__ __forceinline__ void ldsm_x4(uint32_t r[4], uint32_t addr) {
    asm volatile("ldmatrix.sync.aligned.m8n8.x4.shared.b16 {%0,%1,%2,%3}, [%4];"
        : "=r"(r[0]), "=r"(r[1]), "=r"(r[2]), "=r"(r[3]) : "r"(addr));
}
__device__ __forceinline__ void mma_tf32(float d[4], const uint32_t a[4], const uint32_t b[2]) {
    asm volatile(
        "mma.sync.aligned.m16n8k8.row.col.f32.tf32.tf32.f32 "
        "{%0,%1,%2,%3}, {%4,%5,%6,%7}, {%8,%9}, {%0,%1,%2,%3};\n"
        : "+f"(d[0]), "+f"(d[1]), "+f"(d[2]), "+f"(d[3])
        : "r"(a[0]), "r"(a[1]), "r"(a[2]), "r"(a[3]), "r"(b[0]), "r"(b[1]));
}

// ---------------- GEMM core: C[m,n] = alpha * A[m,:]·B[n,:], both K-major ----------------
// Inputs pre-rounded to tf32 bit patterns (no CVT in mainloop).
// 4 warps (2x2), warp tile 64x64, 128x128 block tile, double-buffered.
// EPI: 1 = store tf32r(acc)                    (Q/K proj)
//      2 = transposed tf32r store into Vt      (V proj)
//      3 = store acc * (1/rs[row])             (attention out)
//      4 = store masked tf32r(exp(acc*alpha)), atomicAdd row sums into rs  (scores)
template<int EPI>
__device__ __forceinline__ void gemm_core(
    const float* __restrict__ A, const float* __restrict__ B, float* __restrict__ C,
    int lda, int ldb, long long ldc, int m0, int n0, int kEnd, float alpha,
    float* __restrict__ rs)
{
    extern __shared__ char smraw[];
    const uint32_t sb = (uint32_t)__cvta_generic_to_shared(smraw);
    const int tid  = threadIdx.x;
    const int lane = tid & 31;
    const int warp = tid >> 5;
    const int wm   = warp & 1;          // 64-row slab
    const int wn   = warp >> 1;         // 64-col slab
    const int g    = lane >> 2;         // 0..7
    const int tg   = lane & 3;          // 0..3

    // ldmatrix lane constants
    const int u   = lane & 7;
    const int j   = lane >> 3;
    const int c0A = j >> 1;
    const int rA  = (j & 1) * 8 + u;
    const int c0B = j & 1;
    const int nB  = (j >> 1) * 8 + u;

    float acc[4][8][4];
    #pragma unroll
    for (int mt = 0; mt < 4; mt++)
        #pragma unroll
        for (int nt = 0; nt < 8; nt++)
            #pragma unroll
            for (int i = 0; i < 4; i++) acc[mt][nt][i] = 0.0f;

    const int nk = kEnd / BKK;

    auto load_stage = [&](int s, int k0) {
        #pragma unroll
        for (int i = 0; i < 8; i++) {            // A: 128 rows x 128B, sw128
            int c = tid + i * NTHREADS;
            int row = c >> 3, ch = c & 7;
            uint32_t sa = sb + (uint32_t)(s * A_STG + row * 128 + ((ch ^ (row & 7)) * 16));
            cp_async16(sa, &A[(long long)(m0 + row) * lda + k0 + ch * 4]);
        }
        #pragma unroll
        for (int i = 0; i < 8; i++) {            // B: 128 rows x 128B, sw128
            int c = tid + i * NTHREADS;
            int row = c >> 3, ch = c & 7;
            uint32_t sa = sb + (uint32_t)(SM_B + s * B_STG + row * 128 + ((ch ^ (row & 7)) * 16));
            cp_async16(sa, &B[(long long)(n0 + row) * ldb + k0 + ch * 4]);
        }
    };

    load_stage(0, 0);
    CP_COMMIT();

    for (int it = 0; it < nk; ++it) {
        if (it + 1 < nk) {
            load_stage((it + 1) & 1, (it + 1) * BKK);
            CP_COMMIT();
            CP_WAIT(1);
        } else {
            CP_WAIT(0);
        }
        __syncthreads();

        const uint32_t aBase = sb + (uint32_t)((it & 1) * A_STG);
        const uint32_t bBase = sb + (uint32_t)(SM_B + (it & 1) * B_STG);

        #pragma unroll
        for (int ks = 0; ks < 4; ks++) {
            uint32_t af[4][4], bf[4][4];
            #pragma unroll
            for (int mt = 0; mt < 4; mt++) {
                int row = wm * 64 + mt * 16 + rA;
                ldsm_x4(af[mt], aBase + (uint32_t)(row * 128 + (((c0A + 2 * ks) ^ u) * 16)));
            }
            #pragma unroll
            for (int h = 0; h < 4; h++) {
                int n = wn * 64 + h * 16 + nB;
                ldsm_x4(bf[h], bBase + (uint32_t)(n * 128 + (((c0B + 2 * ks) ^ u) * 16)));
            }
            #pragma unroll
            for (int mt = 0; mt < 4; mt++)
                #pragma unroll
                for (int nt = 0; nt < 8; nt++)
                    mma_tf32(acc[mt][nt], af[mt], &bf[nt >> 1][(nt & 1) * 2]);
        }
        __syncthreads();
    }

    // ---- epilogue ----
    if (EPI == 2) {
        // transpose 128(s) x 128(e) tile through smem -> Vt[e][s], coalesced
        float* sT = (float*)smraw;               // [128 e][stride 132]
        #pragma unroll
        for (int mt = 0; mt < 4; mt++)
            #pragma unroll
            for (int nt = 0; nt < 8; nt++)
                #pragma unroll
                for (int i = 0; i < 4; i++) {
                    int rl = wm * 64 + mt * 16 + g + (i >> 1) * 8;
                    int cl = wn * 64 + nt * 8 + 2 * tg + (i & 1);
                    sT[cl * 132 + rl] = tf32r(acc[mt][nt][i]);
                }
        __syncthreads();
        int b  = m0 >> 11;
        int s0 = m0 & 2047;
        float* dst = C + ((long long)b * EMB + n0) * (long long)SEQ + s0;
        #pragma unroll
        for (int i = 0; i < 32; i++) {
            int idx = tid + i * NTHREADS;
            int er = idx >> 5, sc = (idx & 31) * 4;
            float4 v = *(const float4*)&sT[er * 132 + sc];
            *(float4*)&dst[(long long)er * SEQ + sc] = v;
        }
        __syncthreads();
    } else if (EPI == 4) {
        // scores: P = masked tf32r(exp(acc*alpha)); rowsum += per-row partial sums
        #pragma unroll
        for (int mt = 0; mt < 4; mt++) {
            const int r0 = m0 + wm * 64 + mt * 16 + g;
            const int r1 = r0 + 8;
            float sum0 = 0.0f, sum1 = 0.0f;
            #pragma unroll
            for (int nt = 0; nt < 8; nt++) {
                const int cc = n0 + wn * 64 + nt * 8 + 2 * tg;
                float e0 = __expf(acc[mt][nt][0] * alpha); if (cc     > r0) e0 = 0.0f;
                float e1 = __expf(acc[mt][nt][1] * alpha); if (cc + 1 > r0) e1 = 0.0f;
                float e2 = __expf(acc[mt][nt][2] * alpha); if (cc     > r1) e2 = 0.0f;
                float e3 = __expf(acc[mt][nt][3] * alpha); if (cc + 1 > r1) e3 = 0.0f;
                sum0 += e0 + e1;
                sum1 += e2 + e3;
                *(float2*)&C[(long long)r0 * ldc + cc] = make_float2(tf32r(e0), tf32r(e1));
                *(float2*)&C[(long long)r1 * ldc + cc] = make_float2(tf32r(e2), tf32r(e3));
            }
            sum0 += __shfl_xor_sync(0xffffffffu, sum0, 1);
            sum0 += __shfl_xor_sync(0xffffffffu, sum0, 2);
            sum1 += __shfl_xor_sync(0xffffffffu, sum1, 1);
            sum1 += __shfl_xor_sync(0xffffffffu, sum1, 2);
            if (tg == 0) {
                atomicAdd(&rs[r0], sum0);
                atomicAdd(&rs[r1], sum1);
            }
        }
    } else {
        #pragma unroll
        for (int mt = 0; mt < 4; mt++) {
            const long long r0 = m0 + wm * 64 + mt * 16 + g;
            const long long r1 = r0 + 8;
            float inv0 = 1.0f, inv1 = 1.0f;
            if (EPI == 3) { inv0 = 1.0f / rs[r0]; inv1 = 1.0f / rs[r1]; }
            #pragma unroll
            for (int nt = 0; nt < 8; nt++) {
                const int cc = n0 + wn * 64 + nt * 8 + 2 * tg;
                float2 v0, v1;
                if (EPI == 1) {
                    v0 = make_float2(tf32r(acc[mt][nt][0]), tf32r(acc[mt][nt][1]));
                    v1 = make_float2(tf32r(acc[mt][nt][2]), tf32r(acc[mt][nt][3]));
                } else {           // EPI 3
                    v0 = make_float2(acc[mt][nt][0] * inv0, acc[mt][nt][1] * inv0);
                    v1 = make_float2(acc[mt][nt][2] * inv1, acc[mt][nt][3] * inv1);
                }
                *(float2*)&C[r0 * ldc + cc] = v0;
                *(float2*)&C[r1 * ldc + cc] = v1;
            }
        }
    }
}

// ---------------- kernels ----------------

__global__ void round_kernel(const float* __restrict__ src, int which, int n4) {
    int i = blockIdx.x * blockDim.x + threadIdx.x;
    if (i >= n4) return;
    float* dst = (which == 0) ? g_x : (which == 1) ? g_Wq : (which == 2) ? g_Wk : g_Wv;
    float4 v = ((const float4*)src)[i];
    v.x = tf32r(v.x); v.y = tf32r(v.y); v.z = tf32r(v.z); v.w = tf32r(v.w);
    ((float4*)dst)[i] = v;
}

__global__ void zero_rowsum_kernel() {
    int i = blockIdx.x * blockDim.x + threadIdx.x;
    if (i < BATCH * SEQ) g_rowsum[i] = 0.0f;
}

// grid (KD/BN=8, 8192/BM=64, 3)
__global__ __launch_bounds__(NTHREADS, 2)
void proj_kernel()
{
    int z = blockIdx.z;
    const float* W = (z == 0) ? g_Wq : (z == 1) ? g_Wk : g_Wv;
    if (z == 2)
        gemm_core<2>(g_x, W, g_Vt, EMB, EMB, 0,
                     blockIdx.y * BM, blockIdx.x * BN, EMB, 1.0f, nullptr);
    else
        gemm_core<1>(g_x, W, (z == 0) ? g_Q : g_K, EMB, EMB, KD,
                     blockIdx.y * BM, blockIdx.x * BN, EMB, 1.0f, nullptr);
}

// grid (16, 16, 4); skip fully-masked tiles; epilogue = exp + mask + rowsum
__global__ __launch_bounds__(NTHREADS, 2)
void scores_kernel()
{
    int b = blockIdx.z, bq = blockIdx.y, bs = blockIdx.x;
    if (bs > bq) return;
    gemm_core<4>(g_Q + (long long)b * SEQ * KD, g_K + (long long)b * SEQ * KD,
                 g_P + (long long)b * SEQ * SEQ, KD, KD, SEQ,
                 bq * BM, bs * BN, KD, 0.03125f, g_rowsum + b * SEQ);
}

// grid (8, 16, 4); causal k-trim; epilogue scales by 1/rowsum
__global__ __launch_bounds__(NTHREADS, 2)
void out_kernel(float* __restrict__ out)
{
    int b = blockIdx.z, bq = blockIdx.y;
    gemm_core<3>(g_P + (long long)b * SEQ * SEQ, g_Vt + (long long)b * EMB * SEQ,
                 out + (long long)b * SEQ * EMB, SEQ, SEQ, EMB,
                 bq * BM, blockIdx.x * BN, (bq + 1) * BM, 1.0f, g_rowsum + b * SEQ);
}

// ---------------- launch ----------------
extern "C" void kernel_launch(void* const* d_in, const int* in_sizes, int n_in,
                              void* d_out, int out_size)
{
    const float* x  = (const float*)d_in[0];
    const float* Wq = (const float*)d_in[1];
    const float* Wk = (const float*)d_in[2];
    const float* Wv = (const float*)d_in[3];
    float* out = (float*)d_out;

    cudaFuncSetAttribute(proj_kernel,   cudaFuncAttributeMaxDynamicSharedMemorySize, SMEM_TOTAL);
    cudaFuncSetAttribute(scores_kernel, cudaFuncAttributeMaxDynamicSharedMemorySize, SMEM_TOTAL);
    cudaFuncSetAttribute(out_kernel,    cudaFuncAttributeMaxDynamicSharedMemorySize, SMEM_TOTAL);

    zero_rowsum_kernel<<<(BATCH * SEQ + 255) / 256, 256>>>();
    round_kernel<<<(BATCH * SEQ * EMB / 4 + 255) / 256, 256>>>(x, 0, BATCH * SEQ * EMB / 4);
    round_kernel<<<(KD * EMB / 4 + 255) / 256, 256>>>(Wq, 1, KD * EMB / 4);
    round_kernel<<<(KD * EMB / 4 + 255) / 256, 256>>>(Wk, 2, KD * EMB / 4);
    round_kernel<<<(EMB * EMB / 4 + 255) / 256, 256>>>(Wv, 3, EMB * EMB / 4);

    proj_kernel<<<dim3(KD / BN, (BATCH * SEQ) / BM, 3), NTHREADS, SMEM_TOTAL>>>();
    scores_kernel<<<dim3(SEQ / BN, SEQ / BM, BATCH), NTHREADS, SMEM_TOTAL>>>();
    out_kernel<<<dim3(EMB / BN, SEQ / BM, BATCH), NTHREADS, SMEM_TOTAL>>>(out);
}

// round 9
// speedup vs baseline: 1.2387x; 1.0097x over previous
#include <cuda_runtime.h>
#include <math_constants.h>
#include <cstdint>

#define BATCH 4
#define SEQ   2048
#define EMB   1024
#define KD    1024

#define BM 128
#define BN 128
#define BKK 32                        // k per stage; 32 floats = 128B row

#define A_STG 16384                   // 128 rows x 128B
#define B_STG 16384
#define SM_B  (3 * A_STG)             // 3-stage A, then 3-stage B
#define SMEM_TOTAL (3 * (A_STG + B_STG))   // 98304; 2 CTAs/SM = 192KB <= carveout

#define NTHREADS 128                  // 4 warps, 2(M) x 2(N), warp tile 64x64

// ---------------- static device scratch ----------------
__device__ float g_x [BATCH * SEQ * EMB];
__device__ float g_Wq[KD * EMB];
__device__ float g_Wk[KD * EMB];
__device__ float g_Wv[EMB * EMB];
__device__ float g_Q [BATCH * SEQ * KD];
__device__ float g_K [BATCH * SEQ * KD];
__device__ float g_Vt[BATCH * EMB * SEQ];            // V transposed [b][e][s]
__device__ float g_P [(long long)BATCH * SEQ * SEQ]; // exp(scores), unnormalized
__device__ float g_rowsum[BATCH * SEQ];              // per-row sum of exp

// ---------------- helpers ----------------
__device__ __forceinline__ float tf32r(float x) {
    unsigned r; asm("cvt.rna.tf32.f32 %0, %1;" : "=r"(r) : "f"(x));
    return __uint_as_float(r);
}
__device__ __forceinline__ void cp_async16(uint32_t d, const void* g) {
    asm volatile("cp.async.cg.shared.global [%0], [%1], 16;\n" :: "r"(d), "l"(g));
}
#define CP_COMMIT() asm volatile("cp.async.commit_group;\n" ::: "memory")
#define CP_WAIT(n)  asm volatile("cp.async.wait_group %0;\n" :: "n"(n) : "memory")

__device__ __forceinline__ void ldsm_x4(uint32_t r[4], uint32_t addr) {
    asm volatile("ldmatrix.sync.aligned.m8n8.x4.shared.b16 {%0,%1,%2,%3}, [%4];"
        : "=r"(r[0]), "=r"(r[1]), "=r"(r[2]), "=r"(r[3]) : "r"(addr));
}
__device__ __forceinline__ void mma_tf32(float d[4], const uint32_t a[4], const uint32_t b[2]) {
    asm volatile(
        "mma.sync.aligned.m16n8k8.row.col.f32.tf32.tf32.f32 "
        "{%0,%1,%2,%3}, {%4,%5,%6,%7}, {%8,%9}, {%0,%1,%2,%3};\n"
        : "+f"(d[0]), "+f"(d[1]), "+f"(d[2]), "+f"(d[3])
        : "r"(a[0]), "r"(a[1]), "r"(a[2]), "r"(a[3]), "r"(b[0]), "r"(b[1]));
}

// ---------------- GEMM core: C[m,n] = alpha * A[m,:]·B[n,:], both K-major ----------------
// Inputs pre-rounded to tf32 bit patterns (no CVT in mainloop).
// 4 warps (2x2), warp tile 64x64, 3-stage cp.async pipeline, ONE barrier per k-iter.
// EPI: 1 = store tf32r(acc)                    (Q/K proj)
//      2 = transposed tf32r store into Vt      (V proj)
//      3 = store acc * (1/rs[row])             (attention out)
//      4 = store masked tf32r(exp(acc*alpha)), atomicAdd row sums into rs  (scores)
template<int EPI>
__device__ __forceinline__ void gemm_core(
    const float* __restrict__ A, const float* __restrict__ B, float* __restrict__ C,
    int lda, int ldb, long long ldc, int m0, int n0, int kEnd, float alpha,
    float* __restrict__ rs)
{
    extern __shared__ char smraw[];
    const uint32_t sb = (uint32_t)__cvta_generic_to_shared(smraw);
    const int tid  = threadIdx.x;
    const int lane = tid & 31;
    const int warp = tid >> 5;
    const int wm   = warp & 1;          // 64-row slab
    const int wn   = warp >> 1;         // 64-col slab
    const int g    = lane >> 2;         // 0..7
    const int tg   = lane & 3;          // 0..3

    // ldmatrix lane constants
    const int u   = lane & 7;
    const int j   = lane >> 3;
    const int c0A = j >> 1;
    const int rA  = (j & 1) * 8 + u;
    const int c0B = j & 1;
    const int nB  = (j >> 1) * 8 + u;

    float acc[4][8][4];
    #pragma unroll
    for (int mt = 0; mt < 4; mt++)
        #pragma unroll
        for (int nt = 0; nt < 8; nt++)
            #pragma unroll
            for (int i = 0; i < 4; i++) acc[mt][nt][i] = 0.0f;

    const int nk = kEnd / BKK;          // >= 4 at all call sites

    auto load_stage = [&](int s, int k0) {
        #pragma unroll
        for (int i = 0; i < 8; i++) {            // A: 128 rows x 128B, sw128
            int c = tid + i * NTHREADS;
            int row = c >> 3, ch = c & 7;
            uint32_t sa = sb + (uint32_t)(s * A_STG + row * 128 + ((ch ^ (row & 7)) * 16));
            cp_async16(sa, &A[(long long)(m0 + row) * lda + k0 + ch * 4]);
        }
        #pragma unroll
        for (int i = 0; i < 8; i++) {            // B: 128 rows x 128B, sw128
            int c = tid + i * NTHREADS;
            int row = c >> 3, ch = c & 7;
            uint32_t sa = sb + (uint32_t)(SM_B + s * B_STG + row * 128 + ((ch ^ (row & 7)) * 16));
            cp_async16(sa, &B[(long long)(n0 + row) * ldb + k0 + ch * 4]);
        }
    };

    load_stage(0, 0); CP_COMMIT();
    load_stage(1, BKK); CP_COMMIT();

    for (int it = 0; it < nk; ++it) {
        CP_WAIT(1);                    // stage 'it' landed (a group is committed every iter)
        __syncthreads();               // all warps done with buffer (it-1)%3 AND see stage it

        if (it + 2 < nk) load_stage((it + 2) % 3, (it + 2) * BKK);
        CP_COMMIT();

        const uint32_t aBase = sb + (uint32_t)((it % 3) * A_STG);
        const uint32_t bBase = sb + (uint32_t)(SM_B + (it % 3) * B_STG);

        #pragma unroll
        for (int ks = 0; ks < 4; ks++) {
            uint32_t af[4][4], bf[4][4];
            #pragma unroll
            for (int mt = 0; mt < 4; mt++) {
                int row = wm * 64 + mt * 16 + rA;
                ldsm_x4(af[mt], aBase + (uint32_t)(row * 128 + (((c0A + 2 * ks) ^ u) * 16)));
            }
            #pragma unroll
            for (int h = 0; h < 4; h++) {
                int n = wn * 64 + h * 16 + nB;
                ldsm_x4(bf[h], bBase + (uint32_t)(n * 128 + (((c0B + 2 * ks) ^ u) * 16)));
            }
            #pragma unroll
            for (int mt = 0; mt < 4; mt++)
                #pragma unroll
                for (int nt = 0; nt < 8; nt++)
                    mma_tf32(acc[mt][nt], af[mt], &bf[nt >> 1][(nt & 1) * 2]);
        }
    }

    // ---- epilogue ----
    if (EPI == 2) {
        __syncthreads();                         // smem stages -> transpose buffer reuse
        float* sT = (float*)smraw;               // [128 e][stride 132]
        #pragma unroll
        for (int mt = 0; mt < 4; mt++)
            #pragma unroll
            for (int nt = 0; nt < 8; nt++)
                #pragma unroll
                for (int i = 0; i < 4; i++) {
                    int rl = wm * 64 + mt * 16 + g + (i >> 1) * 8;
                    int cl = wn * 64 + nt * 8 + 2 * tg + (i & 1);
                    sT[cl * 132 + rl] = tf32r(acc[mt][nt][i]);
                }
        __syncthreads();
        int b  = m0 >> 11;
        int s0 = m0 & 2047;
        float* dst = C + ((long long)b * EMB + n0) * (long long)SEQ + s0;
        #pragma unroll
        for (int i = 0; i < 32; i++) {
            int idx = tid + i * NTHREADS;
            int er = idx >> 5, sc = (idx & 31) * 4;
            float4 v = *(const float4*)&sT[er * 132 + sc];
            *(float4*)&dst[(long long)er * SEQ + sc] = v;
        }
    } else if (EPI == 4) {
        // scores: P = masked tf32r(exp(acc*alpha)); rowsum += per-row partial sums
        #pragma unroll
        for (int mt = 0; mt < 4; mt++) {
            const int r0 = m0 + wm * 64 + mt * 16 + g;
            const int r1 = r0 + 8;
            float sum0 = 0.0f, sum1 = 0.0f;
            #pragma unroll
            for (int nt = 0; nt < 8; nt++) {
                const int cc = n0 + wn * 64 + nt * 8 + 2 * tg;
                float e0 = __expf(acc[mt][nt][0] * alpha); if (cc     > r0) e0 = 0.0f;
                float e1 = __expf(acc[mt][nt][1] * alpha); if (cc + 1 > r0) e1 = 0.0f;
                float e2 = __expf(acc[mt][nt][2] * alpha); if (cc     > r1) e2 = 0.0f;
                float e3 = __expf(acc[mt][nt][3] * alpha); if (cc + 1 > r1) e3 = 0.0f;
                sum0 += e0 + e1;
                sum1 += e2 + e3;
                *(float2*)&C[(long long)r0 * ldc + cc] = make_float2(tf32r(e0), tf32r(e1));
                *(float2*)&C[(long long)r1 * ldc + cc] = make_float2(tf32r(e2), tf32r(e3));
            }
            sum0 += __shfl_xor_sync(0xffffffffu, sum0, 1);
            sum0 += __shfl_xor_sync(0xffffffffu, sum0, 2);
            sum1 += __shfl_xor_sync(0xffffffffu, sum1, 1);
            sum1 += __shfl_xor_sync(0xffffffffu, sum1, 2);
            if (tg == 0) {
                atomicAdd(&rs[r0], sum0);
                atomicAdd(&rs[r1], sum1);
            }
        }
    } else {
        #pragma unroll
        for (int mt = 0; mt < 4; mt++) {
            const long long r0 = m0 + wm * 64 + mt * 16 + g;
            const long long r1 = r0 + 8;
            float inv0 = 1.0f, inv1 = 1.0f;
            if (EPI == 3) { inv0 = 1.0f / rs[r0]; inv1 = 1.0f / rs[r1]; }
            #pragma unroll
            for (int nt = 0; nt < 8; nt++) {
                const int cc = n0 + wn * 64 + nt * 8 + 2 * tg;
                float2 v0, v1;
                if (EPI == 1) {
                    v0 = make_float2(tf32r(acc[mt][nt][0]), tf32r(acc[mt][nt][1]));
                    v1 = make_float2(tf32r(acc[mt][nt][2]), tf32r(acc[mt][nt][3]));
                } else {           // EPI 3
                    v0 = make_float2(acc[mt][nt][0] * inv0, acc[mt][nt][1] * inv0);
                    v1 = make_float2(acc[mt][nt][2] * inv1, acc[mt][nt][3] * inv1);
                }
                *(float2*)&C[r0 * ldc + cc] = v0;
                *(float2*)&C[r1 * ldc + cc] = v1;
            }
        }
    }
}

// ---------------- kernels ----------------

// One launch: rounds x, Wq, Wk, Wv into scratch and zeroes rowsum.
#define N4_X  (BATCH * SEQ * EMB / 4)     // 2M float4
#define N4_W  (KD * EMB / 4)              // 256K float4 each
__global__ void prep_kernel(const float* __restrict__ x,  const float* __restrict__ Wq,
                            const float* __restrict__ Wk, const float* __restrict__ Wv)
{
    int i = blockIdx.x * blockDim.x + threadIdx.x;
    if (i < BATCH * SEQ) g_rowsum[i] = 0.0f;

    const float* src; float* dst; int o;
    if (i < N4_X)                    { src = x;  dst = g_x;  o = i; }
    else if (i < N4_X + N4_W)        { src = Wq; dst = g_Wq; o = i - N4_X; }
    else if (i < N4_X + 2 * N4_W)    { src = Wk; dst = g_Wk; o = i - N4_X - N4_W; }
    else if (i < N4_X + 3 * N4_W)    { src = Wv; dst = g_Wv; o = i - N4_X - 2 * N4_W; }
    else return;

    float4 v = ((const float4*)src)[o];
    v.x = tf32r(v.x); v.y = tf32r(v.y); v.z = tf32r(v.z); v.w = tf32r(v.w);
    ((float4*)dst)[o] = v;
}

// grid (KD/BN=8, 8192/BM=64, 3)
__global__ __launch_bounds__(NTHREADS, 2)
void proj_kernel()
{
    int z = blockIdx.z;
    const float* W = (z == 0) ? g_Wq : (z == 1) ? g_Wk : g_Wv;
    if (z == 2)
        gemm_core<2>(g_x, W, g_Vt, EMB, EMB, 0,
                     blockIdx.y * BM, blockIdx.x * BN, EMB, 1.0f, nullptr);
    else
        gemm_core<1>(g_x, W, (z == 0) ? g_Q : g_K, EMB, EMB, KD,
                     blockIdx.y * BM, blockIdx.x * BN, EMB, 1.0f, nullptr);
}

// grid (16, 16, 4); skip fully-masked tiles; epilogue = exp + mask + rowsum
__global__ __launch_bounds__(NTHREADS, 2)
void scores_kernel()
{
    int b = blockIdx.z, bq = blockIdx.y, bs = blockIdx.x;
    if (bs > bq) return;
    gemm_core<4>(g_Q + (long long)b * SEQ * KD, g_K + (long long)b * SEQ * KD,
                 g_P + (long long)b * SEQ * SEQ, KD, KD, SEQ,
                 bq * BM, bs * BN, KD, 0.03125f, g_rowsum + b * SEQ);
}

// grid (8, 16, 4); causal k-trim; epilogue scales by 1/rowsum
__global__ __launch_bounds__(NTHREADS, 2)
void out_kernel(float* __restrict__ out)
{
    int b = blockIdx.z, bq = blockIdx.y;
    gemm_core<3>(g_P + (long long)b * SEQ * SEQ, g_Vt + (long long)b * EMB * SEQ,
                 out + (long long)b * SEQ * EMB, SEQ, SEQ, EMB,
                 bq * BM, blockIdx.x * BN, (bq + 1) * BM, 1.0f, g_rowsum + b * SEQ);
}

// ---------------- launch ----------------
extern "C" void kernel_launch(void* const* d_in, const int* in_sizes, int n_in,
                              void* d_out, int out_size)
{
    const float* x  = (const float*)d_in[0];
    const float* Wq = (const float*)d_in[1];
    const float* Wk = (const float*)d_in[2];
    const float* Wv = (const float*)d_in[3];
    float* out = (float*)d_out;

    cudaFuncSetAttribute(proj_kernel,   cudaFuncAttributeMaxDynamicSharedMemorySize, SMEM_TOTAL);
    cudaFuncSetAttribute(scores_kernel, cudaFuncAttributeMaxDynamicSharedMemorySize, SMEM_TOTAL);
    cudaFuncSetAttribute(out_kernel,    cudaFuncAttributeMaxDynamicSharedMemorySize, SMEM_TOTAL);

    prep_kernel<<<(N4_X + 3 * N4_W + 255) / 256, 256>>>(x, Wq, Wk, Wv);

    proj_kernel<<<dim3(KD / BN, (BATCH * SEQ) / BM, 3), NTHREADS, SMEM_TOTAL>>>();
    scores_kernel<<<dim3(SEQ / BN, SEQ / BM, BATCH), NTHREADS, SMEM_TOTAL>>>();
    out_kernel<<<dim3(EMB / BN, SEQ / BM, BATCH), NTHREADS, SMEM_TOTAL>>>(out);
}

// round 10
// speedup vs baseline: 1.2397x; 1.0008x over previous
#include <cuda_runtime.h>
#include <math_constants.h>
#include <cstdint>

#define BATCH 4
#define SEQ   2048
#define EMB   1024
#define KD    1024

#define BM 128
#define BN 128
#define BKK 32                        // k per stage; 32 floats = 128B row

#define A_STG 16384                   // 128 rows x 128B
#define B_STG 16384
#define SM_B  (3 * A_STG)             // 3-stage A, then 3-stage B
#define SMEM_TOTAL (3 * (A_STG + B_STG))   // 98304; 2 CTAs/SM = 192KB

#define NTHREADS 128                  // 4 warps, 2(M) x 2(N), warp tile 64x64

// ---------------- static device scratch ----------------
__device__ float g_x [BATCH * SEQ * EMB];
__device__ float g_Wq[KD * EMB];
__device__ float g_Wk[KD * EMB];
__device__ float g_Wv[EMB * EMB];
__device__ float g_Q [BATCH * SEQ * KD];
__device__ float g_K [BATCH * SEQ * KD];
__device__ float g_Vt[BATCH * EMB * SEQ];            // V transposed [b][e][s]
__device__ float g_P [(long long)BATCH * SEQ * SEQ]; // exp(scores), unnormalized
__device__ float g_rowsum[BATCH * SEQ];              // per-row sum of exp

// ---------------- helpers ----------------
__device__ __forceinline__ float tf32r(float x) {
    unsigned r; asm("cvt.rna.tf32.f32 %0, %1;" : "=r"(r) : "f"(x));
    return __uint_as_float(r);
}
__device__ __forceinline__ void cp_async16(uint32_t d, const void* g) {
    asm volatile("cp.async.cg.shared.global [%0], [%1], 16;\n" :: "r"(d), "l"(g));
}
#define CP_COMMIT() asm volatile("cp.async.commit_group;\n" ::: "memory")
#define CP_WAIT(n)  asm volatile("cp.async.wait_group %0;\n" :: "n"(n) : "memory")

__device__ __forceinline__ void ldsm_x4(uint32_t r[4], uint32_t addr) {
    asm volatile("ldmatrix.sync.aligned.m8n8.x4.shared.b16 {%0,%1,%2,%3}, [%4];"
        : "=r"(r[0]), "=r"(r[1]), "=r"(r[2]), "=r"(r[3]) : "r"(addr));
}
__device__ __forceinline__ void mma_tf32(float d[4], const uint32_t a[4], const uint32_t b[2]) {
    asm volatile(
        "mma.sync.aligned.m16n8k8.row.col.f32.tf32.tf32.f32 "
        "{%0,%1,%2,%3}, {%4,%5,%6,%7}, {%8,%9}, {%0,%1,%2,%3};\n"
        : "+f"(d[0]), "+f"(d[1]), "+f"(d[2]), "+f"(d[3])
        : "r"(a[0]), "r"(a[1]), "r"(a[2]), "r"(a[3]), "r"(b[0]), "r"(b[1]));
}

// ---------------- GEMM core: C[m,n] = alpha * A[m,:]·B[n,:], both K-major ----------------
// Inputs pre-rounded to tf32 bit patterns (no CVT in mainloop).
// 4 warps (2x2), warp tile 64x64, 3-stage cp.async pipeline, one barrier per k-iter.
// EPI: 1 = store tf32r(acc)                    (Q/K proj)
//      2 = transposed tf32r store into Vt      (V proj)
//      3 = store acc * (1/rs[row])             (attention out)
//      4 = store masked tf32r(exp(acc*alpha)), atomicAdd row sums into rs  (scores)
template<int EPI>
__device__ __forceinline__ void gemm_core(
    const float* __restrict__ A, const float* __restrict__ B, float* __restrict__ C,
    int lda, int ldb, long long ldc, int m0, int n0, int kEnd, float alpha,
    float* __restrict__ rs)
{
    extern __shared__ char smraw[];
    const uint32_t sb = (uint32_t)__cvta_generic_to_shared(smraw);
    const int tid  = threadIdx.x;
    const int lane = tid & 31;
    const int warp = tid >> 5;
    const int wm   = warp & 1;          // 64-row slab
    const int wn   = warp >> 1;         // 64-col slab
    const int g    = lane >> 2;         // 0..7
    const int tg   = lane & 3;          // 0..3

    // ldmatrix lane constants
    const int u   = lane & 7;
    const int j   = lane >> 3;
    const int c0A = j >> 1;
    const int rA  = (j & 1) * 8 + u;
    const int c0B = j & 1;
    const int nB  = (j >> 1) * 8 + u;

    float acc[4][8][4];
    #pragma unroll
    for (int mt = 0; mt < 4; mt++)
        #pragma unroll
        for (int nt = 0; nt < 8; nt++)
            #pragma unroll
            for (int i = 0; i < 4; i++) acc[mt][nt][i] = 0.0f;

    const int nk = kEnd / BKK;          // >= 4 at all call sites

    auto load_stage = [&](int s, int k0) {
        #pragma unroll
        for (int i = 0; i < 8; i++) {            // A: 128 rows x 128B, sw128
            int c = tid + i * NTHREADS;
            int row = c >> 3, ch = c & 7;
            uint32_t sa = sb + (uint32_t)(s * A_STG + row * 128 + ((ch ^ (row & 7)) * 16));
            cp_async16(sa, &A[(long long)(m0 + row) * lda + k0 + ch * 4]);
        }
        #pragma unroll
        for (int i = 0; i < 8; i++) {            // B: 128 rows x 128B, sw128
            int c = tid + i * NTHREADS;
            int row = c >> 3, ch = c & 7;
            uint32_t sa = sb + (uint32_t)(SM_B + s * B_STG + row * 128 + ((ch ^ (row & 7)) * 16));
            cp_async16(sa, &B[(long long)(n0 + row) * ldb + k0 + ch * 4]);
        }
    };

    load_stage(0, 0); CP_COMMIT();
    load_stage(1, BKK); CP_COMMIT();

    for (int it = 0; it < nk; ++it) {
        CP_WAIT(1);                    // stage 'it' landed (a group is committed every iter)
        __syncthreads();               // all warps done with buffer (it-1)%3 AND see stage it

        if (it + 2 < nk) load_stage((it + 2) % 3, (it + 2) * BKK);
        CP_COMMIT();

        const uint32_t aBase = sb + (uint32_t)((it % 3) * A_STG);
        const uint32_t bBase = sb + (uint32_t)(SM_B + (it % 3) * B_STG);

        #pragma unroll
        for (int ks = 0; ks < 4; ks++) {
            uint32_t af[4][4], bf[4][4];
            #pragma unroll
            for (int mt = 0; mt < 4; mt++) {
                int row = wm * 64 + mt * 16 + rA;
                ldsm_x4(af[mt], aBase + (uint32_t)(row * 128 + (((c0A + 2 * ks) ^ u) * 16)));
            }
            #pragma unroll
            for (int h = 0; h < 4; h++) {
                int n = wn * 64 + h * 16 + nB;
                ldsm_x4(bf[h], bBase + (uint32_t)(n * 128 + (((c0B + 2 * ks) ^ u) * 16)));
            }
            #pragma unroll
            for (int mt = 0; mt < 4; mt++)
                #pragma unroll
                for (int nt = 0; nt < 8; nt++)
                    mma_tf32(acc[mt][nt], af[mt], &bf[nt >> 1][(nt & 1) * 2]);
        }
    }

    // ---- epilogue ----
    if (EPI == 2) {
        __syncthreads();                         // smem stages -> transpose buffer reuse
        float* sT = (float*)smraw;               // [128 e][stride 132]
        #pragma unroll
        for (int mt = 0; mt < 4; mt++)
            #pragma unroll
            for (int nt = 0; nt < 8; nt++)
                #pragma unroll
                for (int i = 0; i < 4; i++) {
                    int rl = wm * 64 + mt * 16 + g + (i >> 1) * 8;
                    int cl = wn * 64 + nt * 8 + 2 * tg + (i & 1);
                    sT[cl * 132 + rl] = tf32r(acc[mt][nt][i]);
                }
        __syncthreads();
        int b  = m0 >> 11;
        int s0 = m0 & 2047;
        float* dst = C + ((long long)b * EMB + n0) * (long long)SEQ + s0;
        #pragma unroll
        for (int i = 0; i < 32; i++) {
            int idx = tid + i * NTHREADS;
            int er = idx >> 5, sc = (idx & 31) * 4;
            float4 v = *(const float4*)&sT[er * 132 + sc];
            *(float4*)&dst[(long long)er * SEQ + sc] = v;
        }
    } else if (EPI == 4) {
        // scores: P = masked tf32r(exp(acc*alpha)); rowsum += per-row partial sums
        #pragma unroll
        for (int mt = 0; mt < 4; mt++) {
            const int r0 = m0 + wm * 64 + mt * 16 + g;
            const int r1 = r0 + 8;
            float sum0 = 0.0f, sum1 = 0.0f;
            #pragma unroll
            for (int nt = 0; nt < 8; nt++) {
                const int cc = n0 + wn * 64 + nt * 8 + 2 * tg;
                float e0 = __expf(acc[mt][nt][0] * alpha); if (cc     > r0) e0 = 0.0f;
                float e1 = __expf(acc[mt][nt][1] * alpha); if (cc + 1 > r0) e1 = 0.0f;
                float e2 = __expf(acc[mt][nt][2] * alpha); if (cc     > r1) e2 = 0.0f;
                float e3 = __expf(acc[mt][nt][3] * alpha); if (cc + 1 > r1) e3 = 0.0f;
                sum0 += e0 + e1;
                sum1 += e2 + e3;
                *(float2*)&C[(long long)r0 * ldc + cc] = make_float2(tf32r(e0), tf32r(e1));
                *(float2*)&C[(long long)r1 * ldc + cc] = make_float2(tf32r(e2), tf32r(e3));
            }
            sum0 += __shfl_xor_sync(0xffffffffu, sum0, 1);
            sum0 += __shfl_xor_sync(0xffffffffu, sum0, 2);
            sum1 += __shfl_xor_sync(0xffffffffu, sum1, 1);
            sum1 += __shfl_xor_sync(0xffffffffu, sum1, 2);
            if (tg == 0) {
                atomicAdd(&rs[r0], sum0);
                atomicAdd(&rs[r1], sum1);
            }
        }
    } else {
        #pragma unroll
        for (int mt = 0; mt < 4; mt++) {
            const long long r0 = m0 + wm * 64 + mt * 16 + g;
            const long long r1 = r0 + 8;
            float inv0 = 1.0f, inv1 = 1.0f;
            if (EPI == 3) { inv0 = 1.0f / rs[r0]; inv1 = 1.0f / rs[r1]; }
            #pragma unroll
            for (int nt = 0; nt < 8; nt++) {
                const int cc = n0 + wn * 64 + nt * 8 + 2 * tg;
                float2 v0, v1;
                if (EPI == 1) {
                    v0 = make_float2(tf32r(acc[mt][nt][0]), tf32r(acc[mt][nt][1]));
                    v1 = make_float2(tf32r(acc[mt][nt][2]), tf32r(acc[mt][nt][3]));
                } else {           // EPI 3
                    v0 = make_float2(acc[mt][nt][0] * inv0, acc[mt][nt][1] * inv0);
                    v1 = make_float2(acc[mt][nt][2] * inv1, acc[mt][nt][3] * inv1);
                }
                *(float2*)&C[r0 * ldc + cc] = v0;
                *(float2*)&C[r1 * ldc + cc] = v1;
            }
        }
    }
}

// ---------------- kernels ----------------

// One launch: rounds x, Wq, Wk, Wv into scratch and zeroes rowsum.
#define N4_X  (BATCH * SEQ * EMB / 4)     // 2M float4
#define N4_W  (KD * EMB / 4)              // 256K float4 each
__global__ void prep_kernel(const float* __restrict__ x,  const float* __restrict__ Wq,
                            const float* __restrict__ Wk, const float* __restrict__ Wv)
{
    int i = blockIdx.x * blockDim.x + threadIdx.x;
    if (i < BATCH * SEQ) g_rowsum[i] = 0.0f;

    const float* src; float* dst; int o;
    if (i < N4_X)                    { src = x;  dst = g_x;  o = i; }
    else if (i < N4_X + N4_W)        { src = Wq; dst = g_Wq; o = i - N4_X; }
    else if (i < N4_X + 2 * N4_W)    { src = Wk; dst = g_Wk; o = i - N4_X - N4_W; }
    else if (i < N4_X + 3 * N4_W)    { src = Wv; dst = g_Wv; o = i - N4_X - 2 * N4_W; }
    else return;

    float4 v = ((const float4*)src)[o];
    v.x = tf32r(v.x); v.y = tf32r(v.y); v.z = tf32r(v.z); v.w = tf32r(v.w);
    ((float4*)dst)[o] = v;
}

// grid (KD/BN=8, 8192/BM=64, 3)
__global__ __launch_bounds__(NTHREADS, 2)
void proj_kernel()
{
    int z = blockIdx.z;
    const float* W = (z == 0) ? g_Wq : (z == 1) ? g_Wk : g_Wv;
    if (z == 2)
        gemm_core<2>(g_x, W, g_Vt, EMB, EMB, 0,
                     blockIdx.y * BM, blockIdx.x * BN, EMB, 1.0f, nullptr);
    else
        gemm_core<1>(g_x, W, (z == 0) ? g_Q : g_K, EMB, EMB, KD,
                     blockIdx.y * BM, blockIdx.x * BN, EMB, 1.0f, nullptr);
}

// grid (16, 16, 4); skip fully-masked tiles; epilogue = exp + mask + rowsum
__global__ __launch_bounds__(NTHREADS, 2)
void scores_kernel()
{
    int b = blockIdx.z, bq = blockIdx.y, bs = blockIdx.x;
    if (bs > bq) return;
    gemm_core<4>(g_Q + (long long)b * SEQ * KD, g_K + (long long)b * SEQ * KD,
                 g_P + (long long)b * SEQ * SEQ, KD, KD, SEQ,
                 bq * BM, bs * BN, KD, 0.03125f, g_rowsum + b * SEQ);
}

// grid (8, 16, 4); causal k-trim; epilogue scales by 1/rowsum.
// HEAVY-FIRST: work per tile ~ (bq+1); map y -> 15-y so 64-iter tiles start in
// wave 1 and short tiles backfill (kills the straggler tail seen in R9 ncu).
__global__ __launch_bounds__(NTHREADS, 2)
void out_kernel(float* __restrict__ out)
{
    int b = blockIdx.z;
    int bq = (SEQ / BM - 1) - blockIdx.y;
    gemm_core<3>(g_P + (long long)b * SEQ * SEQ, g_Vt + (long long)b * EMB * SEQ,
                 out + (long long)b * SEQ * EMB, SEQ, SEQ, EMB,
                 bq * BM, blockIdx.x * BN, (bq + 1) * BM, 1.0f, g_rowsum + b * SEQ);
}

// ---------------- launch ----------------
extern "C" void kernel_launch(void* const* d_in, const int* in_sizes, int n_in,
                              void* d_out, int out_size)
{
    const float* x  = (const float*)d_in[0];
    const float* Wq = (const float*)d_in[1];
    const float* Wk = (const float*)d_in[2];
    const float* Wv = (const float*)d_in[3];
    float* out = (float*)d_out;

    cudaFuncSetAttribute(proj_kernel,   cudaFuncAttributeMaxDynamicSharedMemorySize, SMEM_TOTAL);
    cudaFuncSetAttribute(scores_kernel, cudaFuncAttributeMaxDynamicSharedMemorySize, SMEM_TOTAL);
    cudaFuncSetAttribute(out_kernel,    cudaFuncAttributeMaxDynamicSharedMemorySize, SMEM_TOTAL);

    prep_kernel<<<(N4_X + 3 * N4_W + 255) / 256, 256>>>(x, Wq, Wk, Wv);

    proj_kernel<<<dim3(KD / BN, (BATCH * SEQ) / BM, 3), NTHREADS, SMEM_TOTAL>>>();
    scores_kernel<<<dim3(SEQ / BN, SEQ / BM, BATCH), NTHREADS, SMEM_TOTAL>>>();
    out_kernel<<<dim3(EMB / BN, SEQ / BM, BATCH), NTHREADS, SMEM_TOTAL>>>(out);
}

// round 11
// speedup vs baseline: 1.4274x; 1.1514x over previous
#include <cuda_runtime.h>
#include <math_constants.h>
#include <cstdint>

#define BATCH 4
#define SEQ   2048
#define EMB   1024
#define KD    1024

#define BM 128
#define BN 128
#define BKK 32                        // k per stage; 32 floats = 128B row

#define A_STG 16384                   // 128 rows x 128B
#define B_STG 16384
#define SM_B  (3 * A_STG)             // 3-stage A, then 3-stage B
#define SMEM_TOTAL (3 * (A_STG + B_STG))   // 98304; 2 CTAs/SM = 192KB

#define NTHREADS 128                  // 4 warps, 2(M) x 2(N), warp tile 64x64

// ---------------- static device scratch ----------------
__device__ float g_x  [BATCH * SEQ * EMB];
__device__ float g_Wv [EMB * EMB];
__device__ float g_Wqt[EMB * KD];                    // Wq transposed [i][d], tf32
__device__ float g_Wkt[EMB * KD];                    // Wk transposed [i][d], tf32
__device__ float g_Mt [EMB * EMB];                   // Mt[n][k] = sum_d Wk[d][n] Wq[d][k]
__device__ float g_U  [BATCH * SEQ * KD];            // U = x·M  (replaces Q; K deleted)
__device__ float g_Vt [BATCH * EMB * SEQ];           // V transposed [b][e][s]
__device__ float g_P  [(long long)BATCH * SEQ * SEQ];// exp(scores), unnormalized
__device__ float g_rowsum[BATCH * SEQ];              // per-row sum of exp

// ---------------- helpers ----------------
__device__ __forceinline__ float tf32r(float x) {
    unsigned r; asm("cvt.rna.tf32.f32 %0, %1;" : "=r"(r) : "f"(x));
    return __uint_as_float(r);
}
__device__ __forceinline__ void cp_async16(uint32_t d, const void* g) {
    asm volatile("cp.async.cg.shared.global [%0], [%1], 16;\n" :: "r"(d), "l"(g));
}
#define CP_COMMIT() asm volatile("cp.async.commit_group;\n" ::: "memory")
#define CP_WAIT(n)  asm volatile("cp.async.wait_group %0;\n" :: "n"(n) : "memory")

__device__ __forceinline__ void ldsm_x4(uint32_t r[4], uint32_t addr) {
    asm volatile("ldmatrix.sync.aligned.m8n8.x4.shared.b16 {%0,%1,%2,%3}, [%4];"
        : "=r"(r[0]), "=r"(r[1]), "=r"(r[2]), "=r"(r[3]) : "r"(addr));
}
__device__ __forceinline__ void mma_tf32(float d[4], const uint32_t a[4], const uint32_t b[2]) {
    asm volatile(
        "mma.sync.aligned.m16n8k8.row.col.f32.tf32.tf32.f32 "
        "{%0,%1,%2,%3}, {%4,%5,%6,%7}, {%8,%9}, {%0,%1,%2,%3};\n"
        : "+f"(d[0]), "+f"(d[1]), "+f"(d[2]), "+f"(d[3])
        : "r"(a[0]), "r"(a[1]), "r"(a[2]), "r"(a[3]), "r"(b[0]), "r"(b[1]));
}

// ---------------- GEMM core: C[m,n] = alpha * A[m,:]·B[n,:], both K-major ----------------
// Inputs pre-rounded to tf32 bit patterns (no CVT in mainloop).
// 4 warps (2x2), warp tile 64x64, 3-stage cp.async pipeline, one barrier per k-iter.
// EPI: 1 = store tf32r(acc)                    (U proj)
//      2 = transposed tf32r store into Vt      (V proj)
//      3 = store acc * (1/rs[row])             (attention out)
//      4 = store masked tf32r(exp(acc*alpha)), atomicAdd row sums into rs  (scores)
//      5 = atomicAdd acc into C (split-K partial)                          (Mt)
template<int EPI>
__device__ __forceinline__ void gemm_core(
    const float* __restrict__ A, const float* __restrict__ B, float* __restrict__ C,
    int lda, int ldb, long long ldc, int m0, int n0, int kEnd, float alpha,
    float* __restrict__ rs)
{
    extern __shared__ char smraw[];
    const uint32_t sb = (uint32_t)__cvta_generic_to_shared(smraw);
    const int tid  = threadIdx.x;
    const int lane = tid & 31;
    const int warp = tid >> 5;
    const int wm   = warp & 1;          // 64-row slab
    const int wn   = warp >> 1;         // 64-col slab
    const int g    = lane >> 2;         // 0..7
    const int tg   = lane & 3;          // 0..3

    // ldmatrix lane constants
    const int u   = lane & 7;
    const int j   = lane >> 3;
    const int c0A = j >> 1;
    const int rA  = (j & 1) * 8 + u;
    const int c0B = j & 1;
    const int nB  = (j >> 1) * 8 + u;

    float acc[4][8][4];
    #pragma unroll
    for (int mt = 0; mt < 4; mt++)
        #pragma unroll
        for (int nt = 0; nt < 8; nt++)
            #pragma unroll
            for (int i = 0; i < 4; i++) acc[mt][nt][i] = 0.0f;

    const int nk = kEnd / BKK;          // >= 4 at all call sites

    auto load_stage = [&](int s, int k0) {
        #pragma unroll
        for (int i = 0; i < 8; i++) {            // A: 128 rows x 128B, sw128
            int c = tid + i * NTHREADS;
            int row = c >> 3, ch = c & 7;
            uint32_t sa = sb + (uint32_t)(s * A_STG + row * 128 + ((ch ^ (row & 7)) * 16));
            cp_async16(sa, &A[(long long)(m0 + row) * lda + k0 + ch * 4]);
        }
        #pragma unroll
        for (int i = 0; i < 8; i++) {            // B: 128 rows x 128B, sw128
            int c = tid + i * NTHREADS;
            int row = c >> 3, ch = c & 7;
            uint32_t sa = sb + (uint32_t)(SM_B + s * B_STG + row * 128 + ((ch ^ (row & 7)) * 16));
            cp_async16(sa, &B[(long long)(n0 + row) * ldb + k0 + ch * 4]);
        }
    };

    load_stage(0, 0); CP_COMMIT();
    load_stage(1, BKK); CP_COMMIT();

    for (int it = 0; it < nk; ++it) {
        CP_WAIT(1);                    // stage 'it' landed (a group is committed every iter)
        __syncthreads();               // all warps done with buffer (it-1)%3 AND see stage it

        if (it + 2 < nk) load_stage((it + 2) % 3, (it + 2) * BKK);
        CP_COMMIT();

        const uint32_t aBase = sb + (uint32_t)((it % 3) * A_STG);
        const uint32_t bBase = sb + (uint32_t)(SM_B + (it % 3) * B_STG);

        #pragma unroll
        for (int ks = 0; ks < 4; ks++) {
            uint32_t af[4][4], bf[4][4];
            #pragma unroll
            for (int mt = 0; mt < 4; mt++) {
                int row = wm * 64 + mt * 16 + rA;
                ldsm_x4(af[mt], aBase + (uint32_t)(row * 128 + (((c0A + 2 * ks) ^ u) * 16)));
            }
            #pragma unroll
            for (int h = 0; h < 4; h++) {
                int n = wn * 64 + h * 16 + nB;
                ldsm_x4(bf[h], bBase + (uint32_t)(n * 128 + (((c0B + 2 * ks) ^ u) * 16)));
            }
            #pragma unroll
            for (int mt = 0; mt < 4; mt++)
                #pragma unroll
                for (int nt = 0; nt < 8; nt++)
                    mma_tf32(acc[mt][nt], af[mt], &bf[nt >> 1][(nt & 1) * 2]);
        }
    }

    // ---- epilogue ----
    if (EPI == 2) {
        __syncthreads();                         // smem stages -> transpose buffer reuse
        float* sT = (float*)smraw;               // [128 e][stride 132]
        #pragma unroll
        for (int mt = 0; mt < 4; mt++)
            #pragma unroll
            for (int nt = 0; nt < 8; nt++)
                #pragma unroll
                for (int i = 0; i < 4; i++) {
                    int rl = wm * 64 + mt * 16 + g + (i >> 1) * 8;
                    int cl = wn * 64 + nt * 8 + 2 * tg + (i & 1);
                    sT[cl * 132 + rl] = tf32r(acc[mt][nt][i]);
                }
        __syncthreads();
        int b  = m0 >> 11;
        int s0 = m0 & 2047;
        float* dst = C + ((long long)b * EMB + n0) * (long long)SEQ + s0;
        #pragma unroll
        for (int i = 0; i < 32; i++) {
            int idx = tid + i * NTHREADS;
            int er = idx >> 5, sc = (idx & 31) * 4;
            float4 v = *(const float4*)&sT[er * 132 + sc];
            *(float4*)&dst[(long long)er * SEQ + sc] = v;
        }
    } else if (EPI == 4) {
        // scores: P = masked tf32r(exp(acc*alpha)); rowsum += per-row partial sums
        #pragma unroll
        for (int mt = 0; mt < 4; mt++) {
            const int r0 = m0 + wm * 64 + mt * 16 + g;
            const int r1 = r0 + 8;
            float sum0 = 0.0f, sum1 = 0.0f;
            #pragma unroll
            for (int nt = 0; nt < 8; nt++) {
                const int cc = n0 + wn * 64 + nt * 8 + 2 * tg;
                float e0 = __expf(acc[mt][nt][0] * alpha); if (cc     > r0) e0 = 0.0f;
                float e1 = __expf(acc[mt][nt][1] * alpha); if (cc + 1 > r0) e1 = 0.0f;
                float e2 = __expf(acc[mt][nt][2] * alpha); if (cc     > r1) e2 = 0.0f;
                float e3 = __expf(acc[mt][nt][3] * alpha); if (cc + 1 > r1) e3 = 0.0f;
                sum0 += e0 + e1;
                sum1 += e2 + e3;
                *(float2*)&C[(long long)r0 * ldc + cc] = make_float2(tf32r(e0), tf32r(e1));
                *(float2*)&C[(long long)r1 * ldc + cc] = make_float2(tf32r(e2), tf32r(e3));
            }
            sum0 += __shfl_xor_sync(0xffffffffu, sum0, 1);
            sum0 += __shfl_xor_sync(0xffffffffu, sum0, 2);
            sum1 += __shfl_xor_sync(0xffffffffu, sum1, 1);
            sum1 += __shfl_xor_sync(0xffffffffu, sum1, 2);
            if (tg == 0) {
                atomicAdd(&rs[r0], sum0);
                atomicAdd(&rs[r1], sum1);
            }
        }
    } else if (EPI == 5) {
        // split-K partial: accumulate into C with fp32 atomics
        #pragma unroll
        for (int mt = 0; mt < 4; mt++) {
            const long long r0 = m0 + wm * 64 + mt * 16 + g;
            const long long r1 = r0 + 8;
            #pragma unroll
            for (int nt = 0; nt < 8; nt++) {
                const int cc = n0 + wn * 64 + nt * 8 + 2 * tg;
                atomicAdd(&C[r0 * ldc + cc],     acc[mt][nt][0]);
                atomicAdd(&C[r0 * ldc + cc + 1], acc[mt][nt][1]);
                atomicAdd(&C[r1 * ldc + cc],     acc[mt][nt][2]);
                atomicAdd(&C[r1 * ldc + cc + 1], acc[mt][nt][3]);
            }
        }
    } else {
        #pragma unroll
        for (int mt = 0; mt < 4; mt++) {
            const long long r0 = m0 + wm * 64 + mt * 16 + g;
            const long long r1 = r0 + 8;
            float inv0 = 1.0f, inv1 = 1.0f;
            if (EPI == 3) { inv0 = 1.0f / rs[r0]; inv1 = 1.0f / rs[r1]; }
            #pragma unroll
            for (int nt = 0; nt < 8; nt++) {
                const int cc = n0 + wn * 64 + nt * 8 + 2 * tg;
                float2 v0, v1;
                if (EPI == 1) {
                    v0 = make_float2(tf32r(acc[mt][nt][0]), tf32r(acc[mt][nt][1]));
                    v1 = make_float2(tf32r(acc[mt][nt][2]), tf32r(acc[mt][nt][3]));
                } else {           // EPI 3
                    v0 = make_float2(acc[mt][nt][0] * inv0, acc[mt][nt][1] * inv0);
                    v1 = make_float2(acc[mt][nt][2] * inv1, acc[mt][nt][3] * inv1);
                }
                *(float2*)&C[r0 * ldc + cc] = v0;
                *(float2*)&C[r1 * ldc + cc] = v1;
            }
        }
    }
}

// ---------------- kernels ----------------

// prep: round x and Wv into scratch; zero Mt and rowsum.
#define N4_X  (BATCH * SEQ * EMB / 4)     // 2M float4
#define N4_W  (EMB * EMB / 4)             // 256K float4
__global__ void prep_kernel(const float* __restrict__ x, const float* __restrict__ Wv)
{
    int i = blockIdx.x * blockDim.x + threadIdx.x;
    if (i < BATCH * SEQ) g_rowsum[i] = 0.0f;

    if (i < N4_X) {
        float4 v = ((const float4*)x)[i];
        v.x = tf32r(v.x); v.y = tf32r(v.y); v.z = tf32r(v.z); v.w = tf32r(v.w);
        ((float4*)g_x)[i] = v;
    } else if (i < N4_X + N4_W) {
        int o = i - N4_X;
        float4 v = ((const float4*)Wv)[o];
        v.x = tf32r(v.x); v.y = tf32r(v.y); v.z = tf32r(v.z); v.w = tf32r(v.w);
        ((float4*)g_Wv)[o] = v;
    } else if (i < N4_X + 2 * N4_W) {
        int o = i - N4_X - N4_W;
        ((float4*)g_Mt)[o] = make_float4(0.f, 0.f, 0.f, 0.f);
    }
}

// Transpose+round Wq -> Wqt[i][d], Wk -> Wkt[i][d].  grid (32,32,2), block (32,8)
__global__ void transpose_kernel(const float* __restrict__ Wq, const float* __restrict__ Wk)
{
    __shared__ float t[32][33];
    const float* src = blockIdx.z ? Wk : Wq;
    float* dst = blockIdx.z ? g_Wkt : g_Wqt;
    int bx = blockIdx.x * 32, by = blockIdx.y * 32;
    int tx = threadIdx.x, ty = threadIdx.y;
    #pragma unroll
    for (int j = 0; j < 32; j += 8)
        t[ty + j][tx] = tf32r(src[(long long)(by + ty + j) * EMB + bx + tx]);
    __syncthreads();
    #pragma unroll
    for (int j = 0; j < 32; j += 8)
        dst[(long long)(bx + ty + j) * KD + by + tx] = t[tx][ty + j];
}

// Mt[n][k] = sum_d Wk[d][n] * Wq[d][k], split-K over 4 z-slices of 256.
// grid (8, 8, 4)
__global__ __launch_bounds__(NTHREADS, 2)
void mt_kernel()
{
    int kz = blockIdx.z;
    gemm_core<5>(g_Wkt + kz * 256, g_Wqt + kz * 256, g_Mt, KD, KD, EMB,
                 blockIdx.y * BM, blockIdx.x * BN, 256, 1.0f, nullptr);
}

// Round Mt to tf32 bit patterns (it's an MMA operand downstream).
__global__ void mtround_kernel()
{
    int i = blockIdx.x * blockDim.x + threadIdx.x;
    if (i >= N4_W) return;
    float4 v = ((float4*)g_Mt)[i];
    v.x = tf32r(v.x); v.y = tf32r(v.y); v.z = tf32r(v.z); v.w = tf32r(v.w);
    ((float4*)g_Mt)[i] = v;
}

// U = x·M (z=0), Vt = (x·Wv)^T (z=1).  grid (8, 64, 2)
__global__ __launch_bounds__(NTHREADS, 2)
void uv_kernel()
{
    if (blockIdx.z == 0)
        gemm_core<1>(g_x, g_Mt, g_U, EMB, EMB, KD,
                     blockIdx.y * BM, blockIdx.x * BN, EMB, 1.0f, nullptr);
    else
        gemm_core<2>(g_x, g_Wv, g_Vt, EMB, EMB, 0,
                     blockIdx.y * BM, blockIdx.x * BN, EMB, 1.0f, nullptr);
}

// scores[q][s] = U[q,:]·x[s,:] / 32  (x IS the K operand — K projection deleted)
// grid (16, 16, 4); skip fully-masked tiles; epilogue = exp + mask + rowsum
__global__ __launch_bounds__(NTHREADS, 2)
void scores_kernel()
{
    int b = blockIdx.z, bq = blockIdx.y, bs = blockIdx.x;
    if (bs > bq) return;
    gemm_core<4>(g_U + (long long)b * SEQ * KD, g_x + (long long)b * SEQ * EMB,
                 g_P + (long long)b * SEQ * SEQ, KD, EMB, SEQ,
                 bq * BM, bs * BN, KD, 0.03125f, g_rowsum + b * SEQ);
}

// grid (8, 16, 4); causal k-trim; epilogue scales by 1/rowsum
__global__ __launch_bounds__(NTHREADS, 2)
void out_kernel(float* __restrict__ out)
{
    int b = blockIdx.z, bq = blockIdx.y;
    gemm_core<3>(g_P + (long long)b * SEQ * SEQ, g_Vt + (long long)b * EMB * SEQ,
                 out + (long long)b * SEQ * EMB, SEQ, SEQ, EMB,
                 bq * BM, blockIdx.x * BN, (bq + 1) * BM, 1.0f, g_rowsum + b * SEQ);
}

// ---------------- launch ----------------
extern "C" void kernel_launch(void* const* d_in, const int* in_sizes, int n_in,
                              void* d_out, int out_size)
{
    const float* x  = (const float*)d_in[0];
    const float* Wq = (const float*)d_in[1];
    const float* Wk = (const float*)d_in[2];
    const float* Wv = (const float*)d_in[3];
    float* out = (float*)d_out;

    cudaFuncSetAttribute(mt_kernel,     cudaFuncAttributeMaxDynamicSharedMemorySize, SMEM_TOTAL);
    cudaFuncSetAttribute(uv_kernel,     cudaFuncAttributeMaxDynamicSharedMemorySize, SMEM_TOTAL);
    cudaFuncSetAttribute(scores_kernel, cudaFuncAttributeMaxDynamicSharedMemorySize, SMEM_TOTAL);
    cudaFuncSetAttribute(out_kernel,    cudaFuncAttributeMaxDynamicSharedMemorySize, SMEM_TOTAL);

    prep_kernel<<<(N4_X + 2 * N4_W + 255) / 256, 256>>>(x, Wv);
    transpose_kernel<<<dim3(32, 32, 2), dim3(32, 8)>>>(Wq, Wk);
    mt_kernel<<<dim3(EMB / BN, EMB / BM, 4), NTHREADS, SMEM_TOTAL>>>();
    mtround_kernel<<<(N4_W + 255) / 256, 256>>>();
    uv_kernel<<<dim3(KD / BN, (BATCH * SEQ) / BM, 2), NTHREADS, SMEM_TOTAL>>>();
    scores_kernel<<<dim3(SEQ / BN, SEQ / BM, BATCH), NTHREADS, SMEM_TOTAL>>>();
    out_kernel<<<dim3(EMB / BN, SEQ / BM, BATCH), NTHREADS, SMEM_TOTAL>>>(out);
}

// round 12
// speedup vs baseline: 1.4519x; 1.0172x over previous
#include <cuda_runtime.h>
#include <math_constants.h>
#include <cstdint>

#define BATCH 4
#define SEQ   2048
#define EMB   1024
#define KD    1024

#define BM 128
#define BN 128
#define BKK 32                        // k per stage; 32 floats = 128B row

#define A_STG 16384                   // 128 rows x 128B
#define B_STG 16384
#define SM_B  (3 * A_STG)             // 3-stage A, then 3-stage B
#define SMEM_TOTAL (3 * (A_STG + B_STG))   // 98304; 2 CTAs/SM = 192KB

#define NTHREADS 128                  // 4 warps, 2(M) x 2(N), warp tile 64x64

// ---------------- static device scratch ----------------
__device__ float g_x  [BATCH * SEQ * EMB];
__device__ float g_Wv [EMB * EMB];
__device__ float g_Wqt[EMB * KD];                    // Wq transposed [i][d], tf32
__device__ float g_Wkt[EMB * KD];                    // Wk transposed [i][d], tf32
__device__ float g_Mt [EMB * EMB];                   // Mt[n][k] = sum_d Wk[d][n] Wq[d][k]
__device__ float g_U  [BATCH * SEQ * KD];            // U = x·M  (replaces Q; K deleted)
__device__ float g_Vt [BATCH * EMB * SEQ];           // V transposed [b][e][s]
__device__ float g_P  [(long long)BATCH * SEQ * SEQ];// exp(scores), unnormalized
__device__ float g_rowsum[BATCH * SEQ];              // per-row sum of exp

// ---------------- helpers ----------------
__device__ __forceinline__ float tf32r(float x) {
    unsigned r; asm("cvt.rna.tf32.f32 %0, %1;" : "=r"(r) : "f"(x));
    return __uint_as_float(r);
}
__device__ __forceinline__ void cp_async16(uint32_t d, const void* g) {
    asm volatile("cp.async.cg.shared.global [%0], [%1], 16;\n" :: "r"(d), "l"(g));
}
#define CP_COMMIT() asm volatile("cp.async.commit_group;\n" ::: "memory")
#define CP_WAIT(n)  asm volatile("cp.async.wait_group %0;\n" :: "n"(n) : "memory")

__device__ __forceinline__ void ldsm_x4(uint32_t r[4], uint32_t addr) {
    asm volatile("ldmatrix.sync.aligned.m8n8.x4.shared.b16 {%0,%1,%2,%3}, [%4];"
        : "=r"(r[0]), "=r"(r[1]), "=r"(r[2]), "=r"(r[3]) : "r"(addr));
}
__device__ __forceinline__ void mma_tf32(float d[4], const uint32_t a[4], const uint32_t b[2]) {
    asm volatile(
        "mma.sync.aligned.m16n8k8.row.col.f32.tf32.tf32.f32 "
        "{%0,%1,%2,%3}, {%4,%5,%6,%7}, {%8,%9}, {%0,%1,%2,%3};\n"
        : "+f"(d[0]), "+f"(d[1]), "+f"(d[2]), "+f"(d[3])
        : "r"(a[0]), "r"(a[1]), "r"(a[2]), "r"(a[3]), "r"(b[0]), "r"(b[1]));
}

// ---------------- GEMM core: C[m,n] = alpha * A[m,:]·B[n,:], both K-major ----------------
// Inputs pre-rounded to tf32 bit patterns (no CVT in mainloop).
// 4 warps (2x2), warp tile 64x64, 3-stage cp.async pipeline, one barrier per k-iter.
// EPI: 1 = store tf32r(acc)                    (U proj)
//      2 = transposed tf32r store into Vt      (V proj)
//      4 = store masked tf32r(exp(acc*alpha)), atomicAdd row sums into rs  (scores)
//      5 = atomicAdd acc into C (split-K partial, unscaled)                (Mt)
//      6 = atomicAdd acc*(1/rs[row]) into C (split-K partial, scaled)      (out)
template<int EPI>
__device__ __forceinline__ void gemm_core(
    const float* __restrict__ A, const float* __restrict__ B, float* __restrict__ C,
    int lda, int ldb, long long ldc, int m0, int n0, int kEnd, float alpha,
    float* __restrict__ rs)
{
    extern __shared__ char smraw[];
    const uint32_t sb = (uint32_t)__cvta_generic_to_shared(smraw);
    const int tid  = threadIdx.x;
    const int lane = tid & 31;
    const int warp = tid >> 5;
    const int wm   = warp & 1;          // 64-row slab
    const int wn   = warp >> 1;         // 64-col slab
    const int g    = lane >> 2;         // 0..7
    const int tg   = lane & 3;          // 0..3

    // ldmatrix lane constants
    const int u   = lane & 7;
    const int j   = lane >> 3;
    const int c0A = j >> 1;
    const int rA  = (j & 1) * 8 + u;
    const int c0B = j & 1;
    const int nB  = (j >> 1) * 8 + u;

    float acc[4][8][4];
    #pragma unroll
    for (int mt = 0; mt < 4; mt++)
        #pragma unroll
        for (int nt = 0; nt < 8; nt++)
            #pragma unroll
            for (int i = 0; i < 4; i++) acc[mt][nt][i] = 0.0f;

    const int nk = kEnd / BKK;          // >= 4 at all call sites

    auto load_stage = [&](int s, int k0) {
        #pragma unroll
        for (int i = 0; i < 8; i++) {            // A: 128 rows x 128B, sw128
            int c = tid + i * NTHREADS;
            int row = c >> 3, ch = c & 7;
            uint32_t sa = sb + (uint32_t)(s * A_STG + row * 128 + ((ch ^ (row & 7)) * 16));
            cp_async16(sa, &A[(long long)(m0 + row) * lda + k0 + ch * 4]);
        }
        #pragma unroll
        for (int i = 0; i < 8; i++) {            // B: 128 rows x 128B, sw128
            int c = tid + i * NTHREADS;
            int row = c >> 3, ch = c & 7;
            uint32_t sa = sb + (uint32_t)(SM_B + s * B_STG + row * 128 + ((ch ^ (row & 7)) * 16));
            cp_async16(sa, &B[(long long)(n0 + row) * ldb + k0 + ch * 4]);
        }
    };

    load_stage(0, 0); CP_COMMIT();
    load_stage(1, BKK); CP_COMMIT();

    for (int it = 0; it < nk; ++it) {
        CP_WAIT(1);                    // stage 'it' landed (a group is committed every iter)
        __syncthreads();               // all warps done with buffer (it-1)%3 AND see stage it

        if (it + 2 < nk) load_stage((it + 2) % 3, (it + 2) * BKK);
        CP_COMMIT();

        const uint32_t aBase = sb + (uint32_t)((it % 3) * A_STG);
        const uint32_t bBase = sb + (uint32_t)(SM_B + (it % 3) * B_STG);

        #pragma unroll
        for (int ks = 0; ks < 4; ks++) {
            uint32_t af[4][4], bf[4][4];
            #pragma unroll
            for (int mt = 0; mt < 4; mt++) {
                int row = wm * 64 + mt * 16 + rA;
                ldsm_x4(af[mt], aBase + (uint32_t)(row * 128 + (((c0A + 2 * ks) ^ u) * 16)));
            }
            #pragma unroll
            for (int h = 0; h < 4; h++) {
                int n = wn * 64 + h * 16 + nB;
                ldsm_x4(bf[h], bBase + (uint32_t)(n * 128 + (((c0B + 2 * ks) ^ u) * 16)));
            }
            #pragma unroll
            for (int mt = 0; mt < 4; mt++)
                #pragma unroll
                for (int nt = 0; nt < 8; nt++)
                    mma_tf32(acc[mt][nt], af[mt], &bf[nt >> 1][(nt & 1) * 2]);
        }
    }

    // ---- epilogue ----
    if (EPI == 2) {
        __syncthreads();                         // smem stages -> transpose buffer reuse
        float* sT = (float*)smraw;               // [128 e][stride 132]
        #pragma unroll
        for (int mt = 0; mt < 4; mt++)
            #pragma unroll
            for (int nt = 0; nt < 8; nt++)
                #pragma unroll
                for (int i = 0; i < 4; i++) {
                    int rl = wm * 64 + mt * 16 + g + (i >> 1) * 8;
                    int cl = wn * 64 + nt * 8 + 2 * tg + (i & 1);
                    sT[cl * 132 + rl] = tf32r(acc[mt][nt][i]);
                }
        __syncthreads();
        int b  = m0 >> 11;
        int s0 = m0 & 2047;
        float* dst = C + ((long long)b * EMB + n0) * (long long)SEQ + s0;
        #pragma unroll
        for (int i = 0; i < 32; i++) {
            int idx = tid + i * NTHREADS;
            int er = idx >> 5, sc = (idx & 31) * 4;
            float4 v = *(const float4*)&sT[er * 132 + sc];
            *(float4*)&dst[(long long)er * SEQ + sc] = v;
        }
    } else if (EPI == 4) {
        // scores: P = masked tf32r(exp(acc*alpha)); rowsum += per-row partial sums
        #pragma unroll
        for (int mt = 0; mt < 4; mt++) {
            const int r0 = m0 + wm * 64 + mt * 16 + g;
            const int r1 = r0 + 8;
            float sum0 = 0.0f, sum1 = 0.0f;
            #pragma unroll
            for (int nt = 0; nt < 8; nt++) {
                const int cc = n0 + wn * 64 + nt * 8 + 2 * tg;
                float e0 = __expf(acc[mt][nt][0] * alpha); if (cc     > r0) e0 = 0.0f;
                float e1 = __expf(acc[mt][nt][1] * alpha); if (cc + 1 > r0) e1 = 0.0f;
                float e2 = __expf(acc[mt][nt][2] * alpha); if (cc     > r1) e2 = 0.0f;
                float e3 = __expf(acc[mt][nt][3] * alpha); if (cc + 1 > r1) e3 = 0.0f;
                sum0 += e0 + e1;
                sum1 += e2 + e3;
                *(float2*)&C[(long long)r0 * ldc + cc] = make_float2(tf32r(e0), tf32r(e1));
                *(float2*)&C[(long long)r1 * ldc + cc] = make_float2(tf32r(e2), tf32r(e3));
            }
            sum0 += __shfl_xor_sync(0xffffffffu, sum0, 1);
            sum0 += __shfl_xor_sync(0xffffffffu, sum0, 2);
            sum1 += __shfl_xor_sync(0xffffffffu, sum1, 1);
            sum1 += __shfl_xor_sync(0xffffffffu, sum1, 2);
            if (tg == 0) {
                atomicAdd(&rs[r0], sum0);
                atomicAdd(&rs[r1], sum1);
            }
        }
    } else if (EPI == 5 || EPI == 6) {
        // split-K partial: accumulate into C with fp32 atomics (EPI 6 scales by 1/rowsum)
        #pragma unroll
        for (int mt = 0; mt < 4; mt++) {
            const long long r0 = m0 + wm * 64 + mt * 16 + g;
            const long long r1 = r0 + 8;
            float inv0 = 1.0f, inv1 = 1.0f;
            if (EPI == 6) { inv0 = 1.0f / rs[r0]; inv1 = 1.0f / rs[r1]; }
            #pragma unroll
            for (int nt = 0; nt < 8; nt++) {
                const int cc = n0 + wn * 64 + nt * 8 + 2 * tg;
                atomicAdd(&C[r0 * ldc + cc],     acc[mt][nt][0] * inv0);
                atomicAdd(&C[r0 * ldc + cc + 1], acc[mt][nt][1] * inv0);
                atomicAdd(&C[r1 * ldc + cc],     acc[mt][nt][2] * inv1);
                atomicAdd(&C[r1 * ldc + cc + 1], acc[mt][nt][3] * inv1);
            }
        }
    } else {
        // EPI 1: store tf32r(acc)
        #pragma unroll
        for (int mt = 0; mt < 4; mt++) {
            const long long r0 = m0 + wm * 64 + mt * 16 + g;
            const long long r1 = r0 + 8;
            #pragma unroll
            for (int nt = 0; nt < 8; nt++) {
                const int cc = n0 + wn * 64 + nt * 8 + 2 * tg;
                float2 v0 = make_float2(tf32r(acc[mt][nt][0]), tf32r(acc[mt][nt][1]));
                float2 v1 = make_float2(tf32r(acc[mt][nt][2]), tf32r(acc[mt][nt][3]));
                *(float2*)&C[r0 * ldc + cc] = v0;
                *(float2*)&C[r1 * ldc + cc] = v1;
            }
        }
    }
}

// ---------------- kernels ----------------

// prep: round x and Wv into scratch; zero Mt, rowsum, and d_out (poisoned 0xAA).
#define N4_X   (BATCH * SEQ * EMB / 4)     // 2M float4
#define N4_W   (EMB * EMB / 4)             // 256K float4
#define N4_OUT (BATCH * SEQ * EMB / 4)     // 2M float4 (out is [B,S,E] fp32)
__global__ void prep_kernel(const float* __restrict__ x, const float* __restrict__ Wv,
                            float* __restrict__ out)
{
    int i = blockIdx.x * blockDim.x + threadIdx.x;
    if (i < BATCH * SEQ) g_rowsum[i] = 0.0f;
    if (i < N4_OUT) ((float4*)out)[i] = make_float4(0.f, 0.f, 0.f, 0.f);

    if (i < N4_X) {
        float4 v = ((const float4*)x)[i];
        v.x = tf32r(v.x); v.y = tf32r(v.y); v.z = tf32r(v.z); v.w = tf32r(v.w);
        ((float4*)g_x)[i] = v;
    } else if (i < N4_X + N4_W) {
        int o = i - N4_X;
        float4 v = ((const float4*)Wv)[o];
        v.x = tf32r(v.x); v.y = tf32r(v.y); v.z = tf32r(v.z); v.w = tf32r(v.w);
        ((float4*)g_Wv)[o] = v;
    } else if (i < N4_X + 2 * N4_W) {
        int o = i - N4_X - N4_W;
        ((float4*)g_Mt)[o] = make_float4(0.f, 0.f, 0.f, 0.f);
    }
}

// Transpose+round Wq -> Wqt[i][d], Wk -> Wkt[i][d].  grid (32,32,2), block (32,8)
__global__ void transpose_kernel(const float* __restrict__ Wq, const float* __restrict__ Wk)
{
    __shared__ float t[32][33];
    const float* src = blockIdx.z ? Wk : Wq;
    float* dst = blockIdx.z ? g_Wkt : g_Wqt;
    int bx = blockIdx.x * 32, by = blockIdx.y * 32;
    int tx = threadIdx.x, ty = threadIdx.y;
    #pragma unroll
    for (int j = 0; j < 32; j += 8)
        t[ty + j][tx] = tf32r(src[(long long)(by + ty + j) * EMB + bx + tx]);
    __syncthreads();
    #pragma unroll
    for (int j = 0; j < 32; j += 8)
        dst[(long long)(bx + ty + j) * KD + by + tx] = t[tx][ty + j];
}

// Mt[n][k] = sum_d Wk[d][n] * Wq[d][k], split-K over 8 z-slices of 128.
// grid (8, 8, 8), each block nk=4
__global__ __launch_bounds__(NTHREADS, 2)
void mt_kernel()
{
    int kz = blockIdx.z;
    gemm_core<5>(g_Wkt + kz * 128, g_Wqt + kz * 128, g_Mt, KD, KD, EMB,
                 blockIdx.y * BM, blockIdx.x * BN, 128, 1.0f, nullptr);
}

// Round Mt to tf32 bit patterns (it's an MMA operand downstream).
__global__ void mtround_kernel()
{
    int i = blockIdx.x * blockDim.x + threadIdx.x;
    if (i >= N4_W) return;
    float4 v = ((float4*)g_Mt)[i];
    v.x = tf32r(v.x); v.y = tf32r(v.y); v.z = tf32r(v.z); v.w = tf32r(v.w);
    ((float4*)g_Mt)[i] = v;
}

// U = x·M (z=0), Vt = (x·Wv)^T (z=1).  grid (8, 64, 2)
__global__ __launch_bounds__(NTHREADS, 2)
void uv_kernel()
{
    if (blockIdx.z == 0)
        gemm_core<1>(g_x, g_Mt, g_U, EMB, EMB, KD,
                     blockIdx.y * BM, blockIdx.x * BN, EMB, 1.0f, nullptr);
    else
        gemm_core<2>(g_x, g_Wv, g_Vt, EMB, EMB, 0,
                     blockIdx.y * BM, blockIdx.x * BN, EMB, 1.0f, nullptr);
}

// scores[q][s] = U[q,:]·x[s,:] / 32  (x IS the K operand — K projection deleted)
// Triangular-packed grid (136, 1, 4): only live tiles launched.
__global__ __launch_bounds__(NTHREADS, 2)
void scores_kernel()
{
    int b = blockIdx.z;
    int i = blockIdx.x;                  // 0..135
    int bq = 0;
    while ((bq + 1) * (bq + 2) / 2 <= i) bq++;
    int bs = i - bq * (bq + 1) / 2;
    gemm_core<4>(g_U + (long long)b * SEQ * KD, g_x + (long long)b * SEQ * EMB,
                 g_P + (long long)b * SEQ * SEQ, KD, EMB, SEQ,
                 bq * BM, bs * BN, KD, 0.03125f, g_rowsum + b * SEQ);
}

// out: split-K chunks of <= 16 iters (512 s-values) to kill heavy-block stacking.
// grid (8, 40, 4); chunk table per q-tile: ceil((bq+1)/4) chunks.
// Partials are scaled by 1/rowsum (linear) and atomicAdd'ed into the zeroed d_out.
__constant__ int OUT_CUM[17] = {0,1,2,3,4,6,8,10,12,15,18,21,24,28,32,36,40};
__global__ __launch_bounds__(NTHREADS, 2)
void out_kernel(float* __restrict__ out)
{
    int b = blockIdx.z;
    int y = blockIdx.y;                  // 0..39
    int bq = 0;
    while (OUT_CUM[bq + 1] <= y) bq++;
    int ci = y - OUT_CUM[bq];
    int k0 = ci * 512;                               // floats
    int kEnd = min((bq + 1) * BM - k0, 512);         // 128..512, multiple of 128

    gemm_core<6>(g_P + (long long)b * SEQ * SEQ + k0,
                 g_Vt + (long long)b * EMB * SEQ + k0,
                 out + (long long)b * SEQ * EMB, SEQ, SEQ, EMB,
                 bq * BM, blockIdx.x * BN, kEnd, 1.0f, g_rowsum + b * SEQ);
}

// ---------------- launch ----------------
extern "C" void kernel_launch(void* const* d_in, const int* in_sizes, int n_in,
                              void* d_out, int out_size)
{
    const float* x  = (const float*)d_in[0];
    const float* Wq = (const float*)d_in[1];
    const float* Wk = (const float*)d_in[2];
    const float* Wv = (const float*)d_in[3];
    float* out = (float*)d_out;

    cudaFuncSetAttribute(mt_kernel,     cudaFuncAttributeMaxDynamicSharedMemorySize, SMEM_TOTAL);
    cudaFuncSetAttribute(uv_kernel,     cudaFuncAttributeMaxDynamicSharedMemorySize, SMEM_TOTAL);
    cudaFuncSetAttribute(scores_kernel, cudaFuncAttributeMaxDynamicSharedMemorySize, SMEM_TOTAL);
    cudaFuncSetAttribute(out_kernel,    cudaFuncAttributeMaxDynamicSharedMemorySize, SMEM_TOTAL);

    prep_kernel<<<(N4_X + 2 * N4_W + 255) / 256, 256>>>(x, Wv, out);
    transpose_kernel<<<dim3(32, 32, 2), dim3(32, 8)>>>(Wq, Wk);
    mt_kernel<<<dim3(EMB / BN, EMB / BM, 8), NTHREADS, SMEM_TOTAL>>>();
    mtround_kernel<<<(N4_W + 255) / 256, 256>>>();
    uv_kernel<<<dim3(KD / BN, (BATCH * SEQ) / BM, 2), NTHREADS, SMEM_TOTAL>>>();
    scores_kernel<<<dim3(136, 1, BATCH), NTHREADS, SMEM_TOTAL>>>();
    out_kernel<<<dim3(EMB / BN, 40, BATCH), NTHREADS, SMEM_TOTAL>>>(out);
}

// round 13
// speedup vs baseline: 1.4980x; 1.0317x over previous
#include <cuda_runtime.h>
#include <math_constants.h>
#include <cstdint>

#define BATCH 4
#define SEQ   2048
#define EMB   1024
#define KD    1024

#define BM 128
#define BN 128
#define BKK 32                        // k per stage; 32 floats = 128B row

#define A_STG 16384                   // 128 rows x 128B
#define B_STG 16384
#define SM_B  (3 * A_STG)             // 3-stage A, then 3-stage B
#define SMEM_TOTAL (3 * (A_STG + B_STG))   // 98304; 2 CTAs/SM = 192KB

#define NTHREADS 128                  // 4 warps, 2(M) x 2(N), warp tile 64x64

// ---------------- static device scratch ----------------
__device__ float g_x  [BATCH * SEQ * EMB];
__device__ float g_Wv [EMB * EMB];
__device__ float g_Wqt[EMB * KD];                    // Wq transposed [i][d], tf32
__device__ float g_Wkt[EMB * KD];                    // Wk transposed [i][d], tf32
__device__ float g_Mt [EMB * EMB];                   // Mt[n][k] = sum_d Wk[d][n] Wq[d][k]
__device__ float g_U  [BATCH * SEQ * KD];            // U = x·M  (replaces Q; K deleted)
__device__ float g_Vt [BATCH * EMB * SEQ];           // V transposed [b][e][s]
__device__ float g_P  [(long long)BATCH * SEQ * SEQ];// exp(scores), unnormalized
__device__ float g_rowsum[BATCH * SEQ];              // per-row sum of exp

// ---------------- helpers ----------------
__device__ __forceinline__ float tf32r(float x) {
    unsigned r; asm("cvt.rna.tf32.f32 %0, %1;" : "=r"(r) : "f"(x));
    return __uint_as_float(r);
}
__device__ __forceinline__ void cp_async16(uint32_t d, const void* g) {
    asm volatile("cp.async.cg.shared.global [%0], [%1], 16;\n" :: "r"(d), "l"(g));
}
#define CP_COMMIT() asm volatile("cp.async.commit_group;\n" ::: "memory")
#define CP_WAIT(n)  asm volatile("cp.async.wait_group %0;\n" :: "n"(n) : "memory")

__device__ __forceinline__ void ldsm_x4(uint32_t r[4], uint32_t addr) {
    asm volatile("ldmatrix.sync.aligned.m8n8.x4.shared.b16 {%0,%1,%2,%3}, [%4];"
        : "=r"(r[0]), "=r"(r[1]), "=r"(r[2]), "=r"(r[3]) : "r"(addr));
}
__device__ __forceinline__ void mma_tf32(float d[4], const uint32_t a[4], const uint32_t b[2]) {
    asm volatile(
        "mma.sync.aligned.m16n8k8.row.col.f32.tf32.tf32.f32 "
        "{%0,%1,%2,%3}, {%4,%5,%6,%7}, {%8,%9}, {%0,%1,%2,%3};\n"
        : "+f"(d[0]), "+f"(d[1]), "+f"(d[2]), "+f"(d[3])
        : "r"(a[0]), "r"(a[1]), "r"(a[2]), "r"(a[3]), "r"(b[0]), "r"(b[1]));
}

// ---------------- GEMM core: C[m,n] = alpha * A[m,:]·B[n,:], both K-major ----------------
// Inputs pre-rounded to tf32 bit patterns (no CVT in mainloop).
// 4 warps (2x2), warp tile 64x64, 3-stage cp.async pipeline, one barrier per k-iter.
// EPI: 1 = store tf32r(acc)                    (U proj)
//      2 = transposed tf32r store into Vt      (V proj)
//      3 = store acc * (1/rs[row])             (attention out)
//      4 = store masked tf32r(exp(acc*alpha)), atomicAdd row sums into rs  (scores)
//      5 = atomicAdd acc into C (split-K partial, unscaled)                (Mt)
template<int EPI>
__device__ __forceinline__ void gemm_core(
    const float* __restrict__ A, const float* __restrict__ B, float* __restrict__ C,
    int lda, int ldb, long long ldc, int m0, int n0, int kEnd, float alpha,
    float* __restrict__ rs)
{
    extern __shared__ char smraw[];
    const uint32_t sb = (uint32_t)__cvta_generic_to_shared(smraw);
    const int tid  = threadIdx.x;
    const int lane = tid & 31;
    const int warp = tid >> 5;
    const int wm   = warp & 1;          // 64-row slab
    const int wn   = warp >> 1;         // 64-col slab
    const int g    = lane >> 2;         // 0..7
    const int tg   = lane & 3;          // 0..3

    // ldmatrix lane constants
    const int u   = lane & 7;
    const int j   = lane >> 3;
    const int c0A = j >> 1;
    const int rA  = (j & 1) * 8 + u;
    const int c0B = j & 1;
    const int nB  = (j >> 1) * 8 + u;

    float acc[4][8][4];
    #pragma unroll
    for (int mt = 0; mt < 4; mt++)
        #pragma unroll
        for (int nt = 0; nt < 8; nt++)
            #pragma unroll
            for (int i = 0; i < 4; i++) acc[mt][nt][i] = 0.0f;

    const int nk = kEnd / BKK;          // >= 4 at all call sites

    auto load_stage = [&](int s, int k0) {
        #pragma unroll
        for (int i = 0; i < 8; i++) {            // A: 128 rows x 128B, sw128
            int c = tid + i * NTHREADS;
            int row = c >> 3, ch = c & 7;
            uint32_t sa = sb + (uint32_t)(s * A_STG + row * 128 + ((ch ^ (row & 7)) * 16));
            cp_async16(sa, &A[(long long)(m0 + row) * lda + k0 + ch * 4]);
        }
        #pragma unroll
        for (int i = 0; i < 8; i++) {            // B: 128 rows x 128B, sw128
            int c = tid + i * NTHREADS;
            int row = c >> 3, ch = c & 7;
            uint32_t sa = sb + (uint32_t)(SM_B + s * B_STG + row * 128 + ((ch ^ (row & 7)) * 16));
            cp_async16(sa, &B[(long long)(n0 + row) * ldb + k0 + ch * 4]);
        }
    };

    load_stage(0, 0); CP_COMMIT();
    load_stage(1, BKK); CP_COMMIT();

    for (int it = 0; it < nk; ++it) {
        CP_WAIT(1);                    // stage 'it' landed (a group is committed every iter)
        __syncthreads();               // all warps done with buffer (it-1)%3 AND see stage it

        if (it + 2 < nk) load_stage((it + 2) % 3, (it + 2) * BKK);
        CP_COMMIT();

        const uint32_t aBase = sb + (uint32_t)((it % 3) * A_STG);
        const uint32_t bBase = sb + (uint32_t)(SM_B + (it % 3) * B_STG);

        #pragma unroll
        for (int ks = 0; ks < 4; ks++) {
            uint32_t af[4][4], bf[4][4];
            #pragma unroll
            for (int mt = 0; mt < 4; mt++) {
                int row = wm * 64 + mt * 16 + rA;
                ldsm_x4(af[mt], aBase + (uint32_t)(row * 128 + (((c0A + 2 * ks) ^ u) * 16)));
            }
            #pragma unroll
            for (int h = 0; h < 4; h++) {
                int n = wn * 64 + h * 16 + nB;
                ldsm_x4(bf[h], bBase + (uint32_t)(n * 128 + (((c0B + 2 * ks) ^ u) * 16)));
            }
            #pragma unroll
            for (int mt = 0; mt < 4; mt++)
                #pragma unroll
                for (int nt = 0; nt < 8; nt++)
                    mma_tf32(acc[mt][nt], af[mt], &bf[nt >> 1][(nt & 1) * 2]);
        }
    }

    // ---- epilogue ----
    if (EPI == 2) {
        __syncthreads();                         // smem stages -> transpose buffer reuse
        float* sT = (float*)smraw;               // [128 e][stride 132]
        #pragma unroll
        for (int mt = 0; mt < 4; mt++)
            #pragma unroll
            for (int nt = 0; nt < 8; nt++)
                #pragma unroll
                for (int i = 0; i < 4; i++) {
                    int rl = wm * 64 + mt * 16 + g + (i >> 1) * 8;
                    int cl = wn * 64 + nt * 8 + 2 * tg + (i & 1);
                    sT[cl * 132 + rl] = tf32r(acc[mt][nt][i]);
                }
        __syncthreads();
        int b  = m0 >> 11;
        int s0 = m0 & 2047;
        float* dst = C + ((long long)b * EMB + n0) * (long long)SEQ + s0;
        #pragma unroll
        for (int i = 0; i < 32; i++) {
            int idx = tid + i * NTHREADS;
            int er = idx >> 5, sc = (idx & 31) * 4;
            float4 v = *(const float4*)&sT[er * 132 + sc];
            *(float4*)&dst[(long long)er * SEQ + sc] = v;
        }
    } else if (EPI == 4) {
        // scores: P = masked tf32r(exp(acc*alpha)); rowsum += per-row partial sums
        #pragma unroll
        for (int mt = 0; mt < 4; mt++) {
            const int r0 = m0 + wm * 64 + mt * 16 + g;
            const int r1 = r0 + 8;
            float sum0 = 0.0f, sum1 = 0.0f;
            #pragma unroll
            for (int nt = 0; nt < 8; nt++) {
                const int cc = n0 + wn * 64 + nt * 8 + 2 * tg;
                float e0 = __expf(acc[mt][nt][0] * alpha); if (cc     > r0) e0 = 0.0f;
                float e1 = __expf(acc[mt][nt][1] * alpha); if (cc + 1 > r0) e1 = 0.0f;
                float e2 = __expf(acc[mt][nt][2] * alpha); if (cc     > r1) e2 = 0.0f;
                float e3 = __expf(acc[mt][nt][3] * alpha); if (cc + 1 > r1) e3 = 0.0f;
                sum0 += e0 + e1;
                sum1 += e2 + e3;
                *(float2*)&C[(long long)r0 * ldc + cc] = make_float2(tf32r(e0), tf32r(e1));
                *(float2*)&C[(long long)r1 * ldc + cc] = make_float2(tf32r(e2), tf32r(e3));
            }
            sum0 += __shfl_xor_sync(0xffffffffu, sum0, 1);
            sum0 += __shfl_xor_sync(0xffffffffu, sum0, 2);
            sum1 += __shfl_xor_sync(0xffffffffu, sum1, 1);
            sum1 += __shfl_xor_sync(0xffffffffu, sum1, 2);
            if (tg == 0) {
                atomicAdd(&rs[r0], sum0);
                atomicAdd(&rs[r1], sum1);
            }
        }
    } else if (EPI == 5) {
        // split-K partial: accumulate into C with fp32 atomics
        #pragma unroll
        for (int mt = 0; mt < 4; mt++) {
            const long long r0 = m0 + wm * 64 + mt * 16 + g;
            const long long r1 = r0 + 8;
            #pragma unroll
            for (int nt = 0; nt < 8; nt++) {
                const int cc = n0 + wn * 64 + nt * 8 + 2 * tg;
                atomicAdd(&C[r0 * ldc + cc],     acc[mt][nt][0]);
                atomicAdd(&C[r0 * ldc + cc + 1], acc[mt][nt][1]);
                atomicAdd(&C[r1 * ldc + cc],     acc[mt][nt][2]);
                atomicAdd(&C[r1 * ldc + cc + 1], acc[mt][nt][3]);
            }
        }
    } else {
        // EPI 1: store tf32r(acc);  EPI 3: store acc * (1/rowsum)
        #pragma unroll
        for (int mt = 0; mt < 4; mt++) {
            const long long r0 = m0 + wm * 64 + mt * 16 + g;
            const long long r1 = r0 + 8;
            float inv0 = 1.0f, inv1 = 1.0f;
            if (EPI == 3) { inv0 = 1.0f / rs[r0]; inv1 = 1.0f / rs[r1]; }
            #pragma unroll
            for (int nt = 0; nt < 8; nt++) {
                const int cc = n0 + wn * 64 + nt * 8 + 2 * tg;
                float2 v0, v1;
                if (EPI == 1) {
                    v0 = make_float2(tf32r(acc[mt][nt][0]), tf32r(acc[mt][nt][1]));
                    v1 = make_float2(tf32r(acc[mt][nt][2]), tf32r(acc[mt][nt][3]));
                } else {
                    v0 = make_float2(acc[mt][nt][0] * inv0, acc[mt][nt][1] * inv0);
                    v1 = make_float2(acc[mt][nt][2] * inv1, acc[mt][nt][3] * inv1);
                }
                *(float2*)&C[r0 * ldc + cc] = v0;
                *(float2*)&C[r1 * ldc + cc] = v1;
            }
        }
    }
}

// ---------------- kernels ----------------

// prep: blocks [0, 2048) transpose+round Wq/Wk into Wqt/Wkt (32x32 tiles);
//       blocks [2048, ...) round x and Wv, zero Mt, zero rowsum.
#define N4_X   (BATCH * SEQ * EMB / 4)     // 2M float4
#define N4_W   (EMB * EMB / 4)             // 256K float4
#define TP_BLOCKS 2048                     // 1024 tiles per matrix x 2 matrices
__global__ void prep_kernel(const float* __restrict__ x,  const float* __restrict__ Wq,
                            const float* __restrict__ Wk, const float* __restrict__ Wv)
{
    if (blockIdx.x < TP_BLOCKS) {
        __shared__ float t[32][33];
        int which = blockIdx.x >> 10;              // 0 = Wq, 1 = Wk
        int tile  = blockIdx.x & 1023;
        const float* src = which ? Wk : Wq;
        float* dst = which ? g_Wkt : g_Wqt;
        int bx = (tile & 31) * 32, by = (tile >> 5) * 32;
        int tx = threadIdx.x & 31, ty = threadIdx.x >> 5;   // (32,8) from 256 threads
        #pragma unroll
        for (int j = 0; j < 32; j += 8)
            t[ty + j][tx] = tf32r(src[(long long)(by + ty + j) * EMB + bx + tx]);
        __syncthreads();
        #pragma unroll
        for (int j = 0; j < 32; j += 8)
            dst[(long long)(bx + ty + j) * KD + by + tx] = t[tx][ty + j];
        return;
    }

    int i = (blockIdx.x - TP_BLOCKS) * blockDim.x + threadIdx.x;
    if (i < BATCH * SEQ) g_rowsum[i] = 0.0f;

    if (i < N4_X) {
        float4 v = ((const float4*)x)[i];
        v.x = tf32r(v.x); v.y = tf32r(v.y); v.z = tf32r(v.z); v.w = tf32r(v.w);
        ((float4*)g_x)[i] = v;
    } else if (i < N4_X + N4_W) {
        int o = i - N4_X;
        float4 v = ((const float4*)Wv)[o];
        v.x = tf32r(v.x); v.y = tf32r(v.y); v.z = tf32r(v.z); v.w = tf32r(v.w);
        ((float4*)g_Wv)[o] = v;
    } else if (i < N4_X + 2 * N4_W) {
        int o = i - N4_X - N4_W;
        ((float4*)g_Mt)[o] = make_float4(0.f, 0.f, 0.f, 0.f);
    }
}

// Mt[n][k] = sum_d Wk[d][n] * Wq[d][k], split-K over 8 z-slices of 128.
__global__ __launch_bounds__(NTHREADS, 2)
void mt_kernel()
{
    int kz = blockIdx.z;
    gemm_core<5>(g_Wkt + kz * 128, g_Wqt + kz * 128, g_Mt, KD, KD, EMB,
                 blockIdx.y * BM, blockIdx.x * BN, 128, 1.0f, nullptr);
}

// Round Mt to tf32 bit patterns (it's an MMA operand downstream).
__global__ void mtround_kernel()
{
    int i = blockIdx.x * blockDim.x + threadIdx.x;
    if (i >= N4_W) return;
    float4 v = ((float4*)g_Mt)[i];
    v.x = tf32r(v.x); v.y = tf32r(v.y); v.z = tf32r(v.z); v.w = tf32r(v.w);
    ((float4*)g_Mt)[i] = v;
}

// U = x·M (z=0), Vt = (x·Wv)^T (z=1).  grid (8, 64, 2)
__global__ __launch_bounds__(NTHREADS, 2)
void uv_kernel()
{
    if (blockIdx.z == 0)
        gemm_core<1>(g_x, g_Mt, g_U, EMB, EMB, KD,
                     blockIdx.y * BM, blockIdx.x * BN, EMB, 1.0f, nullptr);
    else
        gemm_core<2>(g_x, g_Wv, g_Vt, EMB, EMB, 0,
                     blockIdx.y * BM, blockIdx.x * BN, EMB, 1.0f, nullptr);
}

// scores[q][s] = U[q,:]·x[s,:] / 32  (x IS the K operand — K projection deleted)
// Triangular-packed grid (136, 1, 4): only live tiles launched.
__global__ __launch_bounds__(NTHREADS, 2)
void scores_kernel()
{
    int b = blockIdx.z;
    int i = blockIdx.x;                  // 0..135
    int bq = 0;
    while ((bq + 1) * (bq + 2) / 2 <= i) bq++;
    int bs = i - bq * (bq + 1) / 2;
    gemm_core<4>(g_U + (long long)b * SEQ * KD, g_x + (long long)b * SEQ * EMB,
                 g_P + (long long)b * SEQ * SEQ, KD, EMB, SEQ,
                 bq * BM, bs * BN, KD, 0.03125f, g_rowsum + b * SEQ);
}

// out: antipodal tile pairing — block y handles q-tiles y and 15-y, whose causal
// k-work sums to a constant 17 units -> 256 perfectly uniform blocks, one wave,
// plain deterministic stores (no atomics, no d_out zeroing).  grid (8, 8, 4)
__global__ __launch_bounds__(NTHREADS, 2)
void out_kernel(float* __restrict__ out)
{
    int b = blockIdx.z;
    const float* Pb = g_P  + (long long)b * SEQ * SEQ;
    const float* Vb = g_Vt + (long long)b * EMB * SEQ;
    float* Ob = out + (long long)b * SEQ * EMB;
    float* rs = g_rowsum + b * SEQ;

    int bq1 = blockIdx.y;                       // light: 4..32 iters
    int bq2 = (SEQ / BM - 1) - blockIdx.y;      // heavy: 64..36 iters

    gemm_core<3>(Pb, Vb, Ob, SEQ, SEQ, EMB,
                 bq1 * BM, blockIdx.x * BN, (bq1 + 1) * BM, 1.0f, rs);
    __syncthreads();                            // stage buffers safe for reuse
    gemm_core<3>(Pb, Vb, Ob, SEQ, SEQ, EMB,
                 bq2 * BM, blockIdx.x * BN, (bq2 + 1) * BM, 1.0f, rs);
}

// ---------------- launch ----------------
extern "C" void kernel_launch(void* const* d_in, const int* in_sizes, int n_in,
                              void* d_out, int out_size)
{
    const float* x  = (const float*)d_in[0];
    const float* Wq = (const float*)d_in[1];
    const float* Wk = (const float*)d_in[2];
    const float* Wv = (const float*)d_in[3];
    float* out = (float*)d_out;

    cudaFuncSetAttribute(mt_kernel,     cudaFuncAttributeMaxDynamicSharedMemorySize, SMEM_TOTAL);
    cudaFuncSetAttribute(uv_kernel,     cudaFuncAttributeMaxDynamicSharedMemorySize, SMEM_TOTAL);
    cudaFuncSetAttribute(scores_kernel, cudaFuncAttributeMaxDynamicSharedMemorySize, SMEM_TOTAL);
    cudaFuncSetAttribute(out_kernel,    cudaFuncAttributeMaxDynamicSharedMemorySize, SMEM_TOTAL);

    int ew_blocks = (N4_X + 2 * N4_W + 255) / 256;
    prep_kernel<<<TP_BLOCKS + ew_blocks, 256>>>(x, Wq, Wk, Wv);
    mt_kernel<<<dim3(EMB / BN, EMB / BM, 8), NTHREADS, SMEM_TOTAL>>>();
    mtround_kernel<<<(N4_W + 255) / 256, 256>>>();
    uv_kernel<<<dim3(KD / BN, (BATCH * SEQ) / BM, 2), NTHREADS, SMEM_TOTAL>>>();
    scores_kernel<<<dim3(136, 1, BATCH), NTHREADS, SMEM_TOTAL>>>();
    out_kernel<<<dim3(EMB / BN, 8, BATCH), NTHREADS, SMEM_TOTAL>>>(out);
}

// round 14
// speedup vs baseline: 1.6053x; 1.0717x over previous
#include <cuda_runtime.h>
#include <math_constants.h>
#include <cstdint>

#define BATCH 4
#define SEQ   2048
#define EMB   1024
#define KD    1024

#define BM 128
#define BN 128
#define BKK 32                        // k per stage; 32 floats = 128B row

#define A_STG 16384                   // 128 rows x 128B
#define B_STG 16384
#define SM_B  (3 * A_STG)             // 3-stage A, then 3-stage B
#define SMEM_TOTAL (3 * (A_STG + B_STG))   // 98304; 2 CTAs/SM = 192KB

#define NTHREADS 128                  // 4 warps, 2(M) x 2(N), warp tile 64x64

// ---------------- static device scratch ----------------
__device__ float g_x  [BATCH * SEQ * EMB];
__device__ float g_Wv [EMB * EMB];
__device__ float g_Wqt[EMB * KD];                    // Wq transposed [i][d], tf32
__device__ float g_Wkt[EMB * KD];                    // Wk transposed [i][d], tf32
__device__ float g_Mt [EMB * EMB];                   // Mt[n][k] = sum_d Wk[d][n] Wq[d][k]
__device__ float g_U  [BATCH * SEQ * KD];            // U = x·M  (replaces Q; K deleted)
__device__ float g_Vt [BATCH * EMB * SEQ];           // V transposed [b][e][s]
__device__ float g_P  [(long long)BATCH * SEQ * SEQ];// exp(scores), unnormalized
__device__ float g_rowsum[BATCH * SEQ];              // per-row sum of exp

// readiness counters for intra-kernel dependency gates
__device__ int g_cU[64];             // U row-block (b*16+bq): ready at 8
__device__ int g_cV[32];             // Vt e-block   (b*8+ex):  ready at 16
__device__ int g_cS[64];             // score rowblk (b*16+bq): ready at bq+1

// ---------------- helpers ----------------
__device__ __forceinline__ float tf32r(float x) {
    unsigned r; asm("cvt.rna.tf32.f32 %0, %1;" : "=r"(r) : "f"(x));
    return __uint_as_float(r);
}
__device__ __forceinline__ void cp_async16(uint32_t d, const void* g) {
    asm volatile("cp.async.cg.shared.global [%0], [%1], 16;\n" :: "r"(d), "l"(g));
}
#define CP_COMMIT() asm volatile("cp.async.commit_group;\n" ::: "memory")
#define CP_WAIT(n)  asm volatile("cp.async.wait_group %0;\n" :: "n"(n) : "memory")

__device__ __forceinline__ void ldsm_x4(uint32_t r[4], uint32_t addr) {
    asm volatile("ldmatrix.sync.aligned.m8n8.x4.shared.b16 {%0,%1,%2,%3}, [%4];"
        : "=r"(r[0]), "=r"(r[1]), "=r"(r[2]), "=r"(r[3]) : "r"(addr));
}
__device__ __forceinline__ void mma_tf32(float d[4], const uint32_t a[4], const uint32_t b[2]) {
    asm volatile(
        "mma.sync.aligned.m16n8k8.row.col.f32.tf32.tf32.f32 "
        "{%0,%1,%2,%3}, {%4,%5,%6,%7}, {%8,%9}, {%0,%1,%2,%3};\n"
        : "+f"(d[0]), "+f"(d[1]), "+f"(d[2]), "+f"(d[3])
        : "r"(a[0]), "r"(a[1]), "r"(a[2]), "r"(a[3]), "r"(b[0]), "r"(b[1]));
}
__device__ __forceinline__ int ld_acq(const int* p) {
    int v; asm volatile("ld.global.acquire.gpu.b32 %0, [%1];" : "=r"(v) : "l"(p) : "memory");
    return v;
}
// producer release: every thread fences, then one thread bumps the counter
__device__ __forceinline__ void release_count(int* p) {
    __threadfence();
    __syncthreads();
    if (threadIdx.x == 0) atomicAdd(p, 1);
}
// consumer acquire: tid0 spins, whole block proceeds
__device__ __forceinline__ void wait_count(const int* p, int target) {
    if (threadIdx.x == 0)
        while (ld_acq(p) < target) __nanosleep(100);
    __syncthreads();
}

// ---------------- GEMM core: C[m,n] = alpha * A[m,:]·B[n,:], both K-major ----------------
// Inputs pre-rounded to tf32 bit patterns (no CVT in mainloop).
// 4 warps (2x2), warp tile 64x64, 3-stage cp.async pipeline, one barrier per k-iter.
// EPI: 1 = store tf32r(acc)                    (U proj)
//      2 = transposed tf32r store into Vt      (V proj)
//      3 = store acc * (1/rs[row])             (attention out)
//      4 = store masked tf32r(exp(acc*alpha)), atomicAdd row sums into rs  (scores)
//      5 = atomicAdd acc into C (split-K partial, unscaled)                (Mt)
template<int EPI>
__device__ __forceinline__ void gemm_core(
    const float* __restrict__ A, const float* __restrict__ B, float* __restrict__ C,
    int lda, int ldb, long long ldc, int m0, int n0, int kEnd, float alpha,
    float* __restrict__ rs)
{
    extern __shared__ char smraw[];
    const uint32_t sb = (uint32_t)__cvta_generic_to_shared(smraw);
    const int tid  = threadIdx.x;
    const int lane = tid & 31;
    const int warp = tid >> 5;
    const int wm   = warp & 1;          // 64-row slab
    const int wn   = warp >> 1;         // 64-col slab
    const int g    = lane >> 2;         // 0..7
    const int tg   = lane & 3;          // 0..3

    // ldmatrix lane constants
    const int u   = lane & 7;
    const int j   = lane >> 3;
    const int c0A = j >> 1;
    const int rA  = (j & 1) * 8 + u;
    const int c0B = j & 1;
    const int nB  = (j >> 1) * 8 + u;

    float acc[4][8][4];
    #pragma unroll
    for (int mt = 0; mt < 4; mt++)
        #pragma unroll
        for (int nt = 0; nt < 8; nt++)
            #pragma unroll
            for (int i = 0; i < 4; i++) acc[mt][nt][i] = 0.0f;

    const int nk = kEnd / BKK;          // >= 4 at all call sites

    auto load_stage = [&](int s, int k0) {
        #pragma unroll
        for (int i = 0; i < 8; i++) {            // A: 128 rows x 128B, sw128
            int c = tid + i * NTHREADS;
            int row = c >> 3, ch = c & 7;
            uint32_t sa = sb + (uint32_t)(s * A_STG + row * 128 + ((ch ^ (row & 7)) * 16));
            cp_async16(sa, &A[(long long)(m0 + row) * lda + k0 + ch * 4]);
        }
        #pragma unroll
        for (int i = 0; i < 8; i++) {            // B: 128 rows x 128B, sw128
            int c = tid + i * NTHREADS;
            int row = c >> 3, ch = c & 7;
            uint32_t sa = sb + (uint32_t)(SM_B + s * B_STG + row * 128 + ((ch ^ (row & 7)) * 16));
            cp_async16(sa, &B[(long long)(n0 + row) * ldb + k0 + ch * 4]);
        }
    };

    load_stage(0, 0); CP_COMMIT();
    load_stage(1, BKK); CP_COMMIT();

    for (int it = 0; it < nk; ++it) {
        CP_WAIT(1);                    // stage 'it' landed (a group is committed every iter)
        __syncthreads();               // all warps done with buffer (it-1)%3 AND see stage it

        if (it + 2 < nk) load_stage((it + 2) % 3, (it + 2) * BKK);
        CP_COMMIT();

        const uint32_t aBase = sb + (uint32_t)((it % 3) * A_STG);
        const uint32_t bBase = sb + (uint32_t)(SM_B + (it % 3) * B_STG);

        #pragma unroll
        for (int ks = 0; ks < 4; ks++) {
            uint32_t af[4][4], bf[4][4];
            #pragma unroll
            for (int mt = 0; mt < 4; mt++) {
                int row = wm * 64 + mt * 16 + rA;
                ldsm_x4(af[mt], aBase + (uint32_t)(row * 128 + (((c0A + 2 * ks) ^ u) * 16)));
            }
            #pragma unroll
            for (int h = 0; h < 4; h++) {
                int n = wn * 64 + h * 16 + nB;
                ldsm_x4(bf[h], bBase + (uint32_t)(n * 128 + (((c0B + 2 * ks) ^ u) * 16)));
            }
            #pragma unroll
            for (int mt = 0; mt < 4; mt++)
                #pragma unroll
                for (int nt = 0; nt < 8; nt++)
                    mma_tf32(acc[mt][nt], af[mt], &bf[nt >> 1][(nt & 1) * 2]);
        }
    }

    // ---- epilogue ----
    if (EPI == 2) {
        __syncthreads();                         // smem stages -> transpose buffer reuse
        float* sT = (float*)smraw;               // [128 e][stride 132]
        #pragma unroll
        for (int mt = 0; mt < 4; mt++)
            #pragma unroll
            for (int nt = 0; nt < 8; nt++)
                #pragma unroll
                for (int i = 0; i < 4; i++) {
                    int rl = wm * 64 + mt * 16 + g + (i >> 1) * 8;
                    int cl = wn * 64 + nt * 8 + 2 * tg + (i & 1);
                    sT[cl * 132 + rl] = tf32r(acc[mt][nt][i]);
                }
        __syncthreads();
        int b  = m0 >> 11;
        int s0 = m0 & 2047;
        float* dst = C + ((long long)b * EMB + n0) * (long long)SEQ + s0;
        #pragma unroll
        for (int i = 0; i < 32; i++) {
            int idx = tid + i * NTHREADS;
            int er = idx >> 5, sc = (idx & 31) * 4;
            float4 v = *(const float4*)&sT[er * 132 + sc];
            *(float4*)&dst[(long long)er * SEQ + sc] = v;
        }
    } else if (EPI == 4) {
        // scores: P = masked tf32r(exp(acc*alpha)); rowsum += per-row partial sums
        #pragma unroll
        for (int mt = 0; mt < 4; mt++) {
            const int r0 = m0 + wm * 64 + mt * 16 + g;
            const int r1 = r0 + 8;
            float sum0 = 0.0f, sum1 = 0.0f;
            #pragma unroll
            for (int nt = 0; nt < 8; nt++) {
                const int cc = n0 + wn * 64 + nt * 8 + 2 * tg;
                float e0 = __expf(acc[mt][nt][0] * alpha); if (cc     > r0) e0 = 0.0f;
                float e1 = __expf(acc[mt][nt][1] * alpha); if (cc + 1 > r0) e1 = 0.0f;
                float e2 = __expf(acc[mt][nt][2] * alpha); if (cc     > r1) e2 = 0.0f;
                float e3 = __expf(acc[mt][nt][3] * alpha); if (cc + 1 > r1) e3 = 0.0f;
                sum0 += e0 + e1;
                sum1 += e2 + e3;
                *(float2*)&C[(long long)r0 * ldc + cc] = make_float2(tf32r(e0), tf32r(e1));
                *(float2*)&C[(long long)r1 * ldc + cc] = make_float2(tf32r(e2), tf32r(e3));
            }
            sum0 += __shfl_xor_sync(0xffffffffu, sum0, 1);
            sum0 += __shfl_xor_sync(0xffffffffu, sum0, 2);
            sum1 += __shfl_xor_sync(0xffffffffu, sum1, 1);
            sum1 += __shfl_xor_sync(0xffffffffu, sum1, 2);
            if (tg == 0) {
                atomicAdd(&rs[r0], sum0);
                atomicAdd(&rs[r1], sum1);
            }
        }
    } else if (EPI == 5) {
        // split-K partial: accumulate into C with fp32 atomics
        #pragma unroll
        for (int mt = 0; mt < 4; mt++) {
            const long long r0 = m0 + wm * 64 + mt * 16 + g;
            const long long r1 = r0 + 8;
            #pragma unroll
            for (int nt = 0; nt < 8; nt++) {
                const int cc = n0 + wn * 64 + nt * 8 + 2 * tg;
                atomicAdd(&C[r0 * ldc + cc],     acc[mt][nt][0]);
                atomicAdd(&C[r0 * ldc + cc + 1], acc[mt][nt][1]);
                atomicAdd(&C[r1 * ldc + cc],     acc[mt][nt][2]);
                atomicAdd(&C[r1 * ldc + cc + 1], acc[mt][nt][3]);
            }
        }
    } else {
        // EPI 1: store tf32r(acc);  EPI 3: store acc * (1/rowsum)
        #pragma unroll
        for (int mt = 0; mt < 4; mt++) {
            const long long r0 = m0 + wm * 64 + mt * 16 + g;
            const long long r1 = r0 + 8;
            float inv0 = 1.0f, inv1 = 1.0f;
            if (EPI == 3) { inv0 = 1.0f / rs[r0]; inv1 = 1.0f / rs[r1]; }
            #pragma unroll
            for (int nt = 0; nt < 8; nt++) {
                const int cc = n0 + wn * 64 + nt * 8 + 2 * tg;
                float2 v0, v1;
                if (EPI == 1) {
                    v0 = make_float2(tf32r(acc[mt][nt][0]), tf32r(acc[mt][nt][1]));
                    v1 = make_float2(tf32r(acc[mt][nt][2]), tf32r(acc[mt][nt][3]));
                } else {
                    v0 = make_float2(acc[mt][nt][0] * inv0, acc[mt][nt][1] * inv0);
                    v1 = make_float2(acc[mt][nt][2] * inv1, acc[mt][nt][3] * inv1);
                }
                *(float2*)&C[r0 * ldc + cc] = v0;
                *(float2*)&C[r1 * ldc + cc] = v1;
            }
        }
    }
}

// ---------------- kernels ----------------

// prep: blocks [0, 2048) transpose+round Wq/Wk into Wqt/Wkt (32x32 tiles);
//       blocks [2048, ...) round x and Wv, zero Mt, rowsum, and gate counters.
#define N4_X   (BATCH * SEQ * EMB / 4)     // 2M float4
#define N4_W   (EMB * EMB / 4)             // 256K float4
#define TP_BLOCKS 2048                     // 1024 tiles per matrix x 2 matrices
__global__ void prep_kernel(const float* __restrict__ x,  const float* __restrict__ Wq,
                            const float* __restrict__ Wk, const float* __restrict__ Wv)
{
    if (blockIdx.x < TP_BLOCKS) {
        __shared__ float t[32][33];
        int which = blockIdx.x >> 10;              // 0 = Wq, 1 = Wk
        int tile  = blockIdx.x & 1023;
        const float* src = which ? Wk : Wq;
        float* dst = which ? g_Wkt : g_Wqt;
        int bx = (tile & 31) * 32, by = (tile >> 5) * 32;
        int tx = threadIdx.x & 31, ty = threadIdx.x >> 5;   // (32,8) from 256 threads
        #pragma unroll
        for (int j = 0; j < 32; j += 8)
            t[ty + j][tx] = tf32r(src[(long long)(by + ty + j) * EMB + bx + tx]);
        __syncthreads();
        #pragma unroll
        for (int j = 0; j < 32; j += 8)
            dst[(long long)(bx + ty + j) * KD + by + tx] = t[tx][ty + j];
        return;
    }

    int i = (blockIdx.x - TP_BLOCKS) * blockDim.x + threadIdx.x;
    if (i < BATCH * SEQ) g_rowsum[i] = 0.0f;
    if (i < 64) { g_cU[i] = 0; g_cS[i] = 0; }
    if (i < 32) g_cV[i] = 0;

    if (i < N4_X) {
        float4 v = ((const float4*)x)[i];
        v.x = tf32r(v.x); v.y = tf32r(v.y); v.z = tf32r(v.z); v.w = tf32r(v.w);
        ((float4*)g_x)[i] = v;
    } else if (i < N4_X + N4_W) {
        int o = i - N4_X;
        float4 v = ((const float4*)Wv)[o];
        v.x = tf32r(v.x); v.y = tf32r(v.y); v.z = tf32r(v.z); v.w = tf32r(v.w);
        ((float4*)g_Wv)[o] = v;
    } else if (i < N4_X + 2 * N4_W) {
        int o = i - N4_X - N4_W;
        ((float4*)g_Mt)[o] = make_float4(0.f, 0.f, 0.f, 0.f);
    }
}

// Mt[n][k] = sum_d Wk[d][n] * Wq[d][k], split-K over 8 z-slices of 128.
__global__ __launch_bounds__(NTHREADS, 2)
void mt_kernel()
{
    int kz = blockIdx.z;
    gemm_core<5>(g_Wkt + kz * 128, g_Wqt + kz * 128, g_Mt, KD, KD, EMB,
                 blockIdx.y * BM, blockIdx.x * BN, 128, 1.0f, nullptr);
}

// Round Mt to tf32 bit patterns (it's an MMA operand downstream).
__global__ void mtround_kernel()
{
    int i = blockIdx.x * blockDim.x + threadIdx.x;
    if (i >= N4_W) return;
    float4 v = ((float4*)g_Mt)[i];
    v.x = tf32r(v.x); v.y = tf32r(v.y); v.z = tf32r(v.z); v.w = tf32r(v.w);
    ((float4*)g_Mt)[i] = v;
}

// ---------------- fused main kernel: U-proj | V-proj | scores | out ----------------
// bid ranges (1D grid, dispatch follows bid order — dependency DAG only points
// to lower bids, so spinning consumers always have resident/finished producers):
//   [0,    512): U  = x·Mt tile (by 0..63, bx 0..7)   -> bump cU[by] (ready @8)
//   [512, 1024): Vt = (x·Wv)^T tile                   -> bump cV[b*8+bx] (ready @16)
//   [1024,1568): scores tile (triangular packed)       gate: cU; bump cS[b*16+bq]
//   [1568,1824): out antipodal pair (bq1=y, bq2=15-y)  gate: cV + cS(bq1) + cS(bq2)
#define BID_V   512
#define BID_S   1024
#define BID_O   1568
#define BID_END 1824
__global__ __launch_bounds__(NTHREADS, 2)
void main_kernel(float* __restrict__ out)
{
    int bid = blockIdx.x;

    if (bid < BID_S) {
        int z = bid >> 9;               // 0 = U, 1 = V
        int rem = bid & 511;
        int by = rem >> 3, bx = rem & 7;
        if (z == 0) {
            gemm_core<1>(g_x, g_Mt, g_U, EMB, EMB, KD,
                         by * BM, bx * BN, EMB, 1.0f, nullptr);
            release_count(&g_cU[by]);
        } else {
            gemm_core<2>(g_x, g_Wv, g_Vt, EMB, EMB, 0,
                         by * BM, bx * BN, EMB, 1.0f, nullptr);
            release_count(&g_cV[(by >> 4) * 8 + bx]);
        }
    } else if (bid < BID_O) {
        int i = bid - BID_S;            // 0..543
        int b = i / 136, t = i - b * 136;
        int bq = 0;
        while ((bq + 1) * (bq + 2) / 2 <= t) bq++;
        int bs = t - bq * (bq + 1) / 2;
        wait_count(&g_cU[b * 16 + bq], 8);
        gemm_core<4>(g_U + (long long)b * SEQ * KD, g_x + (long long)b * SEQ * EMB,
                     g_P + (long long)b * SEQ * SEQ, KD, EMB, SEQ,
                     bq * BM, bs * BN, KD, 0.03125f, g_rowsum + b * SEQ);
        release_count(&g_cS[b * 16 + bq]);
    } else {
        int j = bid - BID_O;            // 0..255
        int b = j >> 6;
        int rem = j & 63;
        int y = rem >> 3, ex = rem & 7;
        int bq1 = y, bq2 = 15 - y;

        if (threadIdx.x == 0) {
            while (ld_acq(&g_cV[b * 8 + ex]) < 16)        __nanosleep(100);
            while (ld_acq(&g_cS[b * 16 + bq1]) < bq1 + 1) __nanosleep(100);
            while (ld_acq(&g_cS[b * 16 + bq2]) < bq2 + 1) __nanosleep(100);
        }
        __syncthreads();

        const float* Pb = g_P  + (long long)b * SEQ * SEQ;
        const float* Vb = g_Vt + (long long)b * EMB * SEQ;
        float* Ob = out + (long long)b * SEQ * EMB;
        float* rs = g_rowsum + b * SEQ;

        gemm_core<3>(Pb, Vb, Ob, SEQ, SEQ, EMB,
                     bq1 * BM, ex * BN, (bq1 + 1) * BM, 1.0f, rs);
        __syncthreads();                // stage buffers safe for reuse
        gemm_core<3>(Pb, Vb, Ob, SEQ, SEQ, EMB,
                     bq2 * BM, ex * BN, (bq2 + 1) * BM, 1.0f, rs);
    }
}

// ---------------- launch ----------------
extern "C" void kernel_launch(void* const* d_in, const int* in_sizes, int n_in,
                              void* d_out, int out_size)
{
    const float* x  = (const float*)d_in[0];
    const float* Wq = (const float*)d_in[1];
    const float* Wk = (const float*)d_in[2];
    const float* Wv = (const float*)d_in[3];
    float* out = (float*)d_out;

    cudaFuncSetAttribute(mt_kernel,   cudaFuncAttributeMaxDynamicSharedMemorySize, SMEM_TOTAL);
    cudaFuncSetAttribute(main_kernel, cudaFuncAttributeMaxDynamicSharedMemorySize, SMEM_TOTAL);

    int ew_blocks = (N4_X + 2 * N4_W + 255) / 256;
    prep_kernel<<<TP_BLOCKS + ew_blocks, 256>>>(x, Wq, Wk, Wv);
    mt_kernel<<<dim3(EMB / BN, EMB / BM, 8), NTHREADS, SMEM_TOTAL>>>();
    mtround_kernel<<<(N4_W + 255) / 256, 256>>>();
    main_kernel<<<BID_END, NTHREADS, SMEM_TOTAL>>>(out);
}